// round 2
// baseline (speedup 1.0000x reference)
#include <cuda_runtime.h>

#define BATCH 8192
#define BT 8          // batches per block, main kernel
#define BTV 64        // batches per block, value kernel

// ---- device scratch (no allocations allowed) ----
__device__ __align__(16) float g_Mh[128 * 32];
__device__ __align__(16) float g_Mo[128 * 32];
__device__ __align__(16) float g_G[384 * 96];     // [er|sh|so] -> [common_h|common_o|pre_r]
__device__ __align__(16) float g_Gb[96];
__device__ __align__(16) float g_G2[96 * 128];    // [sh2|so2|r1] -> hr
__device__ __align__(16) float g_b2[128];
__device__ __align__(16) float g_hr[BATCH * 128];

// ============================================================
// Kernel P: fold conv weights
// ============================================================
__global__ void prep_kernel(const float* __restrict__ c1_relW,
                            const float* __restrict__ c1_relb,
                            const float* __restrict__ c1_rootW,
                            const float* __restrict__ c2_relW,
                            const float* __restrict__ c2_relb,
                            const float* __restrict__ c2_rootW) {
    int tid = blockIdx.x * blockDim.x + threadIdx.x;
    int nth = gridDim.x * blockDim.x;

    for (int i = tid; i < 128 * 32; i += nth) {
        g_Mh[i] = c1_rootW[0 * 4096 + i] + c1_rootW[4 * 4096 + i] +
                  c1_rootW[6 * 4096 + i] - c1_relW[6 * 4096 + i];
        g_Mo[i] = c1_rootW[3 * 4096 + i] + c1_rootW[5 * 4096 + i] +
                  c1_rootW[7 * 4096 + i] - c1_relW[7 * 4096 + i];
    }
    // G: rows 0..127 = er, 128..255 = sh, 256..383 = so
    // cols 0..31 = common_h, 32..63 = common_o, 64..95 = pre_r
    for (int i = tid; i < 384 * 96; i += nth) {
        int k = i / 96, c = i % 96;
        int grp = c / 32, cc = c % 32;
        int seg = k / 128, kk = k % 128;
        int idx = kk * 32 + cc;
        float v;
        if (seg == 0) {          // er
            if (grp == 0)      v = c1_relW[0 * 4096 + idx];
            else if (grp == 1) v = c1_relW[3 * 4096 + idx];
            else               v = c1_rootW[1 * 4096 + idx] + c1_rootW[2 * 4096 + idx];
        } else if (seg == 1) {   // sh
            if (grp == 0)      v = c1_relW[6 * 4096 + idx];
            else if (grp == 1) v = c1_relW[5 * 4096 + idx];
            else               v = c1_relW[1 * 4096 + idx];
        } else {                 // so
            if (grp == 0)      v = c1_relW[4 * 4096 + idx];
            else if (grp == 1) v = c1_relW[7 * 4096 + idx];
            else               v = c1_relW[2 * 4096 + idx];
        }
        g_G[i] = v;
    }
    for (int c = tid; c < 96; c += nth) {
        int grp = c / 32, cc = c % 32;
        float v;
        if (grp == 0)      v = c1_relb[0 * 32 + cc] + c1_relb[4 * 32 + cc] + c1_relb[6 * 32 + cc];
        else if (grp == 1) v = c1_relb[3 * 32 + cc] + c1_relb[5 * 32 + cc] + c1_relb[7 * 32 + cc];
        else               v = c1_relb[1 * 32 + cc] + c1_relb[2 * 32 + cc];
        g_Gb[c] = v;
    }
    // G2: rows 0..31 = sh2 (c2_relW[1]), 32..63 = so2 (c2_relW[2]), 64..95 = r1 (root1+root2)
    for (int i = tid; i < 96 * 128; i += nth) {
        int k = i / 128, c = i % 128;
        float v;
        if (k < 32)      v = c2_relW[1 * 4096 + k * 128 + c];
        else if (k < 64) v = c2_relW[2 * 4096 + (k - 32) * 128 + c];
        else             v = c2_rootW[1 * 4096 + (k - 64) * 128 + c] +
                             c2_rootW[2 * 4096 + (k - 64) * 128 + c];
        g_G2[i] = v;
    }
    for (int c = tid; c < 128; c += nth)
        g_b2[c] = c2_relb[1 * 128 + c] + c2_relb[2 * 128 + c];
}

// ============================================================
// Kernel E: embeddings + both conv layers -> hr  (the heavy one)
// ============================================================
// smem layout (floats):
//   sW0h 1792 | sW0o 1792 | sW0r 1536 | sb0h/sb0o/sb0r 256 ea | sb1h/o/r 128 ea
//   sX 3120 | sH1 8192 | sE 4096 | sE2 7680 | sESS 3072 | sVEC 768
// total 33200 floats = 132800 bytes
#define MAIN_SMEM_FLOATS 33200

__global__ void __launch_bounds__(256, 1) main_kernel(
    const float* __restrict__ state,
    const float* __restrict__ wrW0, const float* __restrict__ wrb0,
    const float* __restrict__ wrW1, const float* __restrict__ wrb1,
    const float* __restrict__ whW0, const float* __restrict__ whb0,
    const float* __restrict__ whW1, const float* __restrict__ whb1,
    const float* __restrict__ woW0, const float* __restrict__ wob0,
    const float* __restrict__ woW1, const float* __restrict__ wob1) {
    extern __shared__ float sm[];
    float* sW0h = sm;
    float* sW0o = sW0h + 1792;
    float* sW0r = sW0o + 1792;
    float* sb0h = sW0r + 1536;
    float* sb0o = sb0h + 256;
    float* sb0r = sb0o + 256;
    float* sb1h = sb0r + 256;
    float* sb1o = sb1h + 128;
    float* sb1r = sb1o + 128;
    float* sX   = sb1r + 128;          // BT*390
    float* sH1  = sX + BT * 390;       // 32*256
    float* sE   = sH1 + 8192;          // 32*128
    float* sE2  = sE + 4096;           // BT*960  (per-node e@M, 30 nodes x 32)
    float* sESS = sE2 + BT * 960;      // BT*384  ([er | sh | so])
    float* sVEC = sESS + BT * 384;     // BT*96

    const int tid = threadIdx.x;
    const int b0 = blockIdx.x * BT;

    for (int i = tid; i < 1792; i += 256) { sW0h[i] = whW0[i]; sW0o[i] = woW0[i]; }
    for (int i = tid; i < 1536; i += 256) sW0r[i] = wrW0[i];
    { sb0h[tid] = whb0[tid]; sb0o[tid] = wob0[tid]; sb0r[tid] = wrb0[tid]; }
    if (tid < 128) { sb1h[tid] = whb1[tid]; sb1o[tid] = wob1[tid]; sb1r[tid] = wrb1[tid]; }
    for (int i = tid; i < BT * 390; i += 256) sX[i] = state[b0 * 390 + i];
    for (int i = tid; i < BT * 384; i += 256) sESS[i] = 0.f;
    __syncthreads();

    for (int type = 0; type < 3; ++type) {
        const int npb     = (type == 0) ? 20 : (type == 1) ? 10 : 1;
        const int nodeb   = (type == 1) ? 20 : 0;
        const int K0      = (type == 2) ? 6 : 7;
        const int featoff = (type == 2) ? 0 : 6;
        const float* sW0  = (type == 0) ? sW0h : (type == 1) ? sW0o : sW0r;
        const float* sb0  = (type == 0) ? sb0h : (type == 1) ? sb0o : sb0r;
        const float* sb1v = (type == 0) ? sb1h : (type == 1) ? sb1o : sb1r;
        const float* W1g  = (type == 0) ? whW1 : (type == 1) ? woW1 : wrW1;
        const float* Mg   = (type == 0) ? g_Mh : g_Mo;
        const int nrows   = BT * npb;
        const int sumoff  = (type == 0) ? 128 : 256;

        for (int rt = 0; rt < nrows; rt += 32) {
            const int valid = min(32, nrows - rt);

            // (a) layer1: h1 = relu(x @ W0 + b0), 32 rows x 256 cols
            {
                const int j = tid;
                float w0r[7];
                #pragma unroll
                for (int k = 0; k < 7; ++k) w0r[k] = (k < K0) ? sW0[k * 256 + j] : 0.f;
                const float bias = sb0[j];
                for (int r = 0; r < 32; ++r) {
                    int gr = rt + r; if (gr >= nrows) gr = nrows - 1;
                    const int b = gr / npb, node = nodeb + gr % npb;
                    const float* x = &sX[b * 390 + node * 13 + featoff];
                    float acc = bias;
                    #pragma unroll
                    for (int k = 0; k < 7; ++k) acc += x[k] * w0r[k];
                    sH1[r * 256 + j] = fmaxf(acc, 0.f);
                }
            }
            __syncthreads();

            // (b) layer2: e = relu(h1 @ W1 + b1), 32x128, K=256; 4x4 register blocking
            {
                const int warp = tid >> 5, lane = tid & 31;
                const int r0 = warp * 4;
                float acc[4][4];
                #pragma unroll
                for (int i = 0; i < 4; ++i)
                    #pragma unroll
                    for (int j = 0; j < 4; ++j) acc[i][j] = 0.f;
                const float* W1p = W1g + lane;
                for (int k = 0; k < 256; k += 4) {
                    float4 a[4];
                    #pragma unroll
                    for (int i = 0; i < 4; ++i)
                        a[i] = *reinterpret_cast<const float4*>(&sH1[(r0 + i) * 256 + k]);
                    #pragma unroll
                    for (int kk = 0; kk < 4; ++kk) {
                        float w[4];
                        #pragma unroll
                        for (int j = 0; j < 4; ++j) w[j] = W1p[(k + kk) * 128 + 32 * j];
                        #pragma unroll
                        for (int i = 0; i < 4; ++i) {
                            const float av = (kk == 0) ? a[i].x : (kk == 1) ? a[i].y :
                                             (kk == 2) ? a[i].z : a[i].w;
                            #pragma unroll
                            for (int j = 0; j < 4; ++j) acc[i][j] += av * w[j];
                        }
                    }
                }
                #pragma unroll
                for (int i = 0; i < 4; ++i)
                    #pragma unroll
                    for (int j = 0; j < 4; ++j) {
                        const int c = lane + 32 * j;
                        sE[(r0 + i) * 128 + c] = fmaxf(acc[i][j] + sb1v[c], 0.f);
                    }
            }
            __syncthreads();

            // (c) post-process
            if (type < 2) {
                if (tid < 128) {   // accumulate sh/so per batch
                    const int c = tid;
                    int r = 0;
                    while (r < valid) {
                        const int gr = rt + r;
                        const int b = gr / npb;
                        const int rend = min(valid, r + (npb - gr % npb));
                        float s = 0.f;
                        for (int rr = r; rr < rend; ++rr) s += sE[rr * 128 + c];
                        sESS[b * 384 + sumoff + c] += s;
                        r = rend;
                    }
                }
                {   // e2 = e @ M (128 -> 32), one float4 of cols per thread
                    const int r = tid >> 3, cq = tid & 7;
                    if (r < valid) {
                        const int gr = rt + r;
                        const int b = gr / npb, node = nodeb + gr % npb;
                        float4 a4 = make_float4(0.f, 0.f, 0.f, 0.f);
                        const float4* M4 = reinterpret_cast<const float4*>(Mg) + cq;
                        const float* Er = &sE[r * 128];
                        #pragma unroll 4
                        for (int k = 0; k < 128; ++k) {
                            const float av = Er[k];
                            const float4 w4 = M4[k * 8];
                            a4.x += av * w4.x; a4.y += av * w4.y;
                            a4.z += av * w4.z; a4.w += av * w4.w;
                        }
                        *(reinterpret_cast<float4*>(&sE2[b * 960 + node * 32]) + cq) = a4;
                    }
                }
            } else {
                for (int i = tid; i < BT * 128; i += 256) {
                    const int b = i >> 7, c = i & 127;
                    sESS[b * 384 + c] = sE[b * 128 + c];   // er
                }
            }
            __syncthreads();
        }
    }

    // (d)+(e) conv1 commons + per-node relu sums -> [sh2|so2|r1]
    {
        const int b = tid >> 5, c0 = tid & 31;
        float a0 = g_Gb[c0], a1 = g_Gb[c0 + 32], a2 = g_Gb[c0 + 64];
        const float* in = &sESS[b * 384];
        for (int k = 0; k < 384; ++k) {
            const float av = in[k];
            a0 += av * g_G[k * 96 + c0];
            a1 += av * g_G[k * 96 + c0 + 32];
            a2 += av * g_G[k * 96 + c0 + 64];
        }
        float sh2 = 0.f, so2 = 0.f;
        const float* e2b = &sE2[b * 960];
        #pragma unroll
        for (int n = 0; n < 20; ++n) sh2 += fmaxf(a0 + e2b[n * 32 + c0], 0.f);
        #pragma unroll
        for (int n = 0; n < 10; ++n) so2 += fmaxf(a1 + e2b[(20 + n) * 32 + c0], 0.f);
        sVEC[b * 96 + c0]      = sh2;
        sVEC[b * 96 + 32 + c0] = so2;
        sVEC[b * 96 + 64 + c0] = fmaxf(a2, 0.f);
    }
    __syncthreads();

    // (f) hr = relu([sh2|so2|r1] @ G2 + b2)
    {
        const int b = tid >> 5, cg = tid & 31;
        float acc[4];
        #pragma unroll
        for (int j = 0; j < 4; ++j) acc[j] = g_b2[cg + 32 * j];
        const float* in = &sVEC[b * 96];
        for (int k = 0; k < 96; ++k) {
            const float av = in[k];
            #pragma unroll
            for (int j = 0; j < 4; ++j) acc[j] += av * g_G2[k * 128 + cg + 32 * j];
        }
        #pragma unroll
        for (int j = 0; j < 4; ++j)
            g_hr[(b0 + b) * 128 + cg + 32 * j] = fmaxf(acc[j], 0.f);
    }
}

// ============================================================
// Kernel V: value MLP 128->256->128->1
// ============================================================
// smem: sHR 8192 | sP 16384 | sQ 64*129=8256 -> 32832 floats = 131328 B
#define VAL_SMEM_FLOATS 32832

__global__ void __launch_bounds__(256, 1) value_kernel(
    const float* __restrict__ vW0, const float* __restrict__ vb0,
    const float* __restrict__ vW1, const float* __restrict__ vb1,
    const float* __restrict__ vW2, const float* __restrict__ vb2,
    float* __restrict__ out) {
    extern __shared__ float sm[];
    float* sHR = sm;              // 64x128
    float* sP  = sHR + 8192;      // 64x256
    float* sQ  = sP + 16384;      // 64x129 (padded)

    const int tid = threadIdx.x;
    const int b0 = blockIdx.x * BTV;

    for (int i = tid; i < BTV * 128; i += 256) sHR[i] = g_hr[b0 * 128 + i];
    __syncthreads();

    // P = relu(HR @ vW0 + b0): 64x256, K=128; 8x8 blocking
    {
        const int warp = tid >> 5, lane = tid & 31;
        const int r0 = warp * 8;
        float acc[8][8];
        #pragma unroll
        for (int i = 0; i < 8; ++i)
            #pragma unroll
            for (int j = 0; j < 8; ++j) acc[i][j] = 0.f;
        const float* Wp = vW0 + lane;
        for (int k = 0; k < 128; ++k) {
            float a[8], w[8];
            #pragma unroll
            for (int i = 0; i < 8; ++i) a[i] = sHR[(r0 + i) * 128 + k];
            #pragma unroll
            for (int j = 0; j < 8; ++j) w[j] = Wp[k * 256 + 32 * j];
            #pragma unroll
            for (int i = 0; i < 8; ++i)
                #pragma unroll
                for (int j = 0; j < 8; ++j) acc[i][j] += a[i] * w[j];
        }
        #pragma unroll
        for (int i = 0; i < 8; ++i)
            #pragma unroll
            for (int j = 0; j < 8; ++j) {
                const int c = lane + 32 * j;
                sP[(r0 + i) * 256 + c] = fmaxf(acc[i][j] + vb0[c], 0.f);
            }
    }
    __syncthreads();

    // Q = relu(P @ vW1 + b1): 64x128, K=256; 8x4 blocking
    {
        const int warp = tid >> 5, lane = tid & 31;
        const int r0 = warp * 8;
        float acc[8][4];
        #pragma unroll
        for (int i = 0; i < 8; ++i)
            #pragma unroll
            for (int j = 0; j < 4; ++j) acc[i][j] = 0.f;
        const float* Wp = vW1 + lane;
        for (int k = 0; k < 256; ++k) {
            float a[8], w[4];
            #pragma unroll
            for (int i = 0; i < 8; ++i) a[i] = sP[(r0 + i) * 256 + k];
            #pragma unroll
            for (int j = 0; j < 4; ++j) w[j] = Wp[k * 128 + 32 * j];
            #pragma unroll
            for (int i = 0; i < 8; ++i)
                #pragma unroll
                for (int j = 0; j < 4; ++j) acc[i][j] += a[i] * w[j];
        }
        #pragma unroll
        for (int i = 0; i < 8; ++i)
            #pragma unroll
            for (int j = 0; j < 4; ++j) {
                const int c = lane + 32 * j;
                sQ[(r0 + i) * 129 + c] = fmaxf(acc[i][j] + vb1[c], 0.f);
            }
    }
    __syncthreads();

    if (tid < BTV) {
        float acc = vb2[0];
        const float* q = &sQ[tid * 129];
        #pragma unroll 4
        for (int k = 0; k < 128; ++k) acc += q[k] * vW2[k];
        out[b0 + tid] = acc;
    }
}

// ============================================================
extern "C" void kernel_launch(void* const* d_in, const int* in_sizes, int n_in,
                              void* d_out, int out_size) {
    const float* state   = (const float*)d_in[0];
    const float* wrW0    = (const float*)d_in[2];
    const float* wrb0    = (const float*)d_in[3];
    const float* wrW1    = (const float*)d_in[4];
    const float* wrb1    = (const float*)d_in[5];
    const float* whW0    = (const float*)d_in[6];
    const float* whb0    = (const float*)d_in[7];
    const float* whW1    = (const float*)d_in[8];
    const float* whb1    = (const float*)d_in[9];
    const float* woW0    = (const float*)d_in[10];
    const float* wob0    = (const float*)d_in[11];
    const float* woW1    = (const float*)d_in[12];
    const float* wob1    = (const float*)d_in[13];
    const float* c1_relW = (const float*)d_in[14];
    const float* c1_relb = (const float*)d_in[15];
    const float* c1_rootW= (const float*)d_in[16];
    const float* c2_relW = (const float*)d_in[17];
    const float* c2_relb = (const float*)d_in[18];
    const float* c2_rootW= (const float*)d_in[19];
    const float* vW0     = (const float*)d_in[20];
    const float* vb0     = (const float*)d_in[21];
    const float* vW1     = (const float*)d_in[22];
    const float* vb1     = (const float*)d_in[23];
    const float* vW2     = (const float*)d_in[24];
    const float* vb2     = (const float*)d_in[25];
    float* out = (float*)d_out;

    cudaFuncSetAttribute(main_kernel, cudaFuncAttributeMaxDynamicSharedMemorySize,
                         MAIN_SMEM_FLOATS * 4);
    cudaFuncSetAttribute(value_kernel, cudaFuncAttributeMaxDynamicSharedMemorySize,
                         VAL_SMEM_FLOATS * 4);

    prep_kernel<<<64, 256>>>(c1_relW, c1_relb, c1_rootW, c2_relW, c2_relb, c2_rootW);

    main_kernel<<<BATCH / BT, 256, MAIN_SMEM_FLOATS * 4>>>(
        state, wrW0, wrb0, wrW1, wrb1, whW0, whb0, whW1, whb1,
        woW0, wob0, woW1, wob1);

    value_kernel<<<BATCH / BTV, 256, VAL_SMEM_FLOATS * 4>>>(
        vW0, vb0, vW1, vb1, vW2, vb2, out);
}

// round 3
// speedup vs baseline: 1.3202x; 1.3202x over previous
#include <cuda_runtime.h>

#define BATCH 8192
#define BT 8            // batches per block
#define NT 512          // threads per block

// ---- device scratch (no allocations allowed) ----
__device__ __align__(16) float g_Mh[128 * 32];
__device__ __align__(16) float g_Mo[128 * 32];
__device__ __align__(16) float g_G[384 * 96];     // [er|sh|so] -> [common_h|common_o|pre_r]
__device__ __align__(16) float g_Gb[96];
__device__ __align__(16) float g_G2[96 * 128];    // [sh2|so2|r1] -> hr
__device__ __align__(16) float g_b2[128];

// ============================================================
// Kernel P: fold conv weights
// ============================================================
__global__ void prep_kernel(const float* __restrict__ c1_relW,
                            const float* __restrict__ c1_relb,
                            const float* __restrict__ c1_rootW,
                            const float* __restrict__ c2_relW,
                            const float* __restrict__ c2_relb,
                            const float* __restrict__ c2_rootW) {
    int tid = blockIdx.x * blockDim.x + threadIdx.x;
    int nth = gridDim.x * blockDim.x;

    for (int i = tid; i < 128 * 32; i += nth) {
        g_Mh[i] = c1_rootW[0 * 4096 + i] + c1_rootW[4 * 4096 + i] +
                  c1_rootW[6 * 4096 + i] - c1_relW[6 * 4096 + i];
        g_Mo[i] = c1_rootW[3 * 4096 + i] + c1_rootW[5 * 4096 + i] +
                  c1_rootW[7 * 4096 + i] - c1_relW[7 * 4096 + i];
    }
    for (int i = tid; i < 384 * 96; i += nth) {
        int k = i / 96, c = i % 96;
        int grp = c / 32, cc = c % 32;
        int seg = k / 128, kk = k % 128;
        int idx = kk * 32 + cc;
        float v;
        if (seg == 0) {          // er
            if (grp == 0)      v = c1_relW[0 * 4096 + idx];
            else if (grp == 1) v = c1_relW[3 * 4096 + idx];
            else               v = c1_rootW[1 * 4096 + idx] + c1_rootW[2 * 4096 + idx];
        } else if (seg == 1) {   // sh
            if (grp == 0)      v = c1_relW[6 * 4096 + idx];
            else if (grp == 1) v = c1_relW[5 * 4096 + idx];
            else               v = c1_relW[1 * 4096 + idx];
        } else {                 // so
            if (grp == 0)      v = c1_relW[4 * 4096 + idx];
            else if (grp == 1) v = c1_relW[7 * 4096 + idx];
            else               v = c1_relW[2 * 4096 + idx];
        }
        g_G[i] = v;
    }
    for (int c = tid; c < 96; c += nth) {
        int grp = c / 32, cc = c % 32;
        float v;
        if (grp == 0)      v = c1_relb[0 * 32 + cc] + c1_relb[4 * 32 + cc] + c1_relb[6 * 32 + cc];
        else if (grp == 1) v = c1_relb[3 * 32 + cc] + c1_relb[5 * 32 + cc] + c1_relb[7 * 32 + cc];
        else               v = c1_relb[1 * 32 + cc] + c1_relb[2 * 32 + cc];
        g_Gb[c] = v;
    }
    for (int i = tid; i < 96 * 128; i += nth) {
        int k = i / 128, c = i % 128;
        float v;
        if (k < 32)      v = c2_relW[1 * 4096 + k * 128 + c];
        else if (k < 64) v = c2_relW[2 * 4096 + (k - 32) * 128 + c];
        else             v = c2_rootW[1 * 4096 + (k - 64) * 128 + c] +
                             c2_rootW[2 * 4096 + (k - 64) * 128 + c];
        g_G2[i] = v;
    }
    for (int c = tid; c < 128; c += nth)
        g_b2[c] = c2_relb[1 * 128 + c] + c2_relb[2 * 128 + c];
}

// ============================================================
// Kernel M: everything else, fused (embeddings, convs, value MLP)
// ============================================================
// smem (floats):
//  sW0h 1792 | sW0o 1792 | sW0r 1536 | b0 x3 768 | b1 x3 384 |
//  sXh 1120 | sXo 560 | sXr 48 | sH1 8192 | sE 8192 | sE2 7680 | sESS 3072 | sVEC 768
#define MAIN_SMEM_FLOATS 35904   // 143616 bytes

__global__ void __launch_bounds__(NT, 1) main_kernel(
    const float* __restrict__ state,
    const float* __restrict__ wrW0, const float* __restrict__ wrb0,
    const float* __restrict__ wrW1, const float* __restrict__ wrb1,
    const float* __restrict__ whW0, const float* __restrict__ whb0,
    const float* __restrict__ whW1, const float* __restrict__ whb1,
    const float* __restrict__ woW0, const float* __restrict__ wob0,
    const float* __restrict__ woW1, const float* __restrict__ wob1,
    const float* __restrict__ vW0, const float* __restrict__ vb0,
    const float* __restrict__ vW1, const float* __restrict__ vb1,
    const float* __restrict__ vW2, const float* __restrict__ vb2,
    float* __restrict__ out) {
    extern __shared__ float sm[];
    float* sW0h = sm;                  // 7x256
    float* sW0o = sW0h + 1792;
    float* sW0r = sW0o + 1792;         // 6x256
    float* sb0h = sW0r + 1536;
    float* sb0o = sb0h + 256;
    float* sb0r = sb0o + 256;
    float* sb1h = sb0r + 256;
    float* sb1o = sb1h + 128;
    float* sb1r = sb1o + 128;
    float* sXh  = sb1r + 128;          // 8 x 20 x 7
    float* sXo  = sXh + BT * 140;      // 8 x 10 x 7
    float* sXr  = sXo + BT * 70;       // 8 x 6
    float* sH1  = sXr + BT * 6;        // 64 x 128 (K-half tile)
    float* sE   = sH1 + 8192;          // 64 x 128
    float* sE2  = sE + 8192;           // 8 x 30 x 32
    float* sESS = sE2 + BT * 960;      // 8 x 384  [er|sh|so]
    float* sVEC = sESS + BT * 384;     // 8 x 96

    const int tid = threadIdx.x;
    const int b0 = blockIdx.x * BT;
    const int lane = tid & 31, warp = tid >> 5;

    // ---- stage weights + inputs ----
    for (int i = tid; i < 1792; i += NT) { sW0h[i] = whW0[i]; sW0o[i] = woW0[i]; }
    for (int i = tid; i < 1536; i += NT) sW0r[i] = wrW0[i];
    if (tid < 256) { sb0h[tid] = whb0[tid]; sb0o[tid] = wob0[tid]; sb0r[tid] = wrb0[tid]; }
    else if (tid < 384) {
        int c = tid - 256;
        sb1h[c] = whb1[c]; sb1o[c] = wob1[c]; sb1r[c] = wrb1[c];
    }
    for (int i = tid; i < BT * 140; i += NT) {
        int b = i / 140, r = i % 140, nl = r / 7, f = r % 7;
        sXh[i] = state[(b0 + b) * 390 + nl * 13 + 6 + f];
    }
    for (int i = tid; i < BT * 70; i += NT) {
        int b = i / 70, r = i % 70, nl = r / 7, f = r % 7;
        sXo[i] = state[(b0 + b) * 390 + (20 + nl) * 13 + 6 + f];
    }
    if (tid < BT * 6) {
        int b = tid / 6, f = tid % 6;
        sXr[tid] = state[(b0 + b) * 390 + f];
    }
    for (int i = tid; i < BT * 384; i += NT) sESS[i] = 0.f;
    __syncthreads();

    // ---- embeddings + conv1 per-node terms ----
#pragma unroll
    for (int type = 0; type < 3; ++type) {
        const int npb     = (type == 0) ? 20 : (type == 1) ? 10 : 1;
        const int nodeb   = (type == 1) ? 20 : 0;
        const int K0      = (type == 2) ? 6 : 7;
        const int xstride = (type == 0) ? 140 : (type == 1) ? 70 : 6;
        const float* sW0  = (type == 0) ? sW0h : (type == 1) ? sW0o : sW0r;
        const float* sb0v = (type == 0) ? sb0h : (type == 1) ? sb0o : sb0r;
        const float* sb1v = (type == 0) ? sb1h : (type == 1) ? sb1o : sb1r;
        const float* W1g  = (type == 0) ? whW1 : (type == 1) ? woW1 : wrW1;
        const float* Mg   = (type == 0) ? g_Mh : g_Mo;
        const float* sXt  = (type == 0) ? sXh : (type == 1) ? sXo : sXr;
        const int nrows   = BT * npb;
        const int sumoff  = (type == 0) ? 128 : 256;

        for (int rt = 0; rt < nrows; rt += 64) {
            const int valid = min(64, nrows - rt);
            float acc[4][4];
#pragma unroll
            for (int i = 0; i < 4; ++i)
#pragma unroll
                for (int j = 0; j < 4; ++j) acc[i][j] = 0.f;

            for (int half = 0; half < 2; ++half) {
                // (a) layer1: h1 = relu(x @ W0 + b0), 64 rows x 128 cols (K-half)
                {
                    const int colg = tid & 127, rg = tid >> 7;
                    float w0r[7];
#pragma unroll
                    for (int k = 0; k < 7; ++k)
                        w0r[k] = (k < K0) ? sW0[k * 256 + half * 128 + colg] : 0.f;
                    const float bias = sb0v[half * 128 + colg];
#pragma unroll 4
                    for (int rr = 0; rr < 16; ++rr) {
                        int r = rg * 16 + rr;
                        int gr = rt + r; if (gr >= nrows) gr = nrows - 1;
                        const int b = gr / npb, nl = gr - b * npb;
                        const float* x = &sXt[b * xstride + nl * 7];
                        float a = bias;
#pragma unroll
                        for (int k = 0; k < 7; ++k)
                            if (k < K0) a += x[k] * w0r[k];
                        sH1[r * 128 + colg] = fmaxf(a, 0.f);
                    }
                }
                __syncthreads();

                // (b) layer2 partial: acc += h1_half @ W1_half  (64x128, K=128)
                {
                    const int r0 = warp * 4, c0 = lane * 4;
                    const float* Wp = W1g + half * 128 * 128 + c0;
#pragma unroll 2
                    for (int k = 0; k < 128; k += 4) {
                        float a[4][4];
#pragma unroll
                        for (int i = 0; i < 4; ++i) {
                            float4 t = *reinterpret_cast<const float4*>(&sH1[(r0 + i) * 128 + k]);
                            a[i][0] = t.x; a[i][1] = t.y; a[i][2] = t.z; a[i][3] = t.w;
                        }
#pragma unroll
                        for (int kk = 0; kk < 4; ++kk) {
                            float4 w = *reinterpret_cast<const float4*>(&Wp[(k + kk) * 128]);
#pragma unroll
                            for (int i = 0; i < 4; ++i) {
                                acc[i][0] += a[i][kk] * w.x;
                                acc[i][1] += a[i][kk] * w.y;
                                acc[i][2] += a[i][kk] * w.z;
                                acc[i][3] += a[i][kk] * w.w;
                            }
                        }
                    }
                }
                __syncthreads();   // sH1 reused next half
            }

            // (b-finish) bias + relu -> sE
            {
                const int r0 = warp * 4, c0 = lane * 4;
                float4 bb = *reinterpret_cast<const float4*>(&sb1v[c0]);
#pragma unroll
                for (int i = 0; i < 4; ++i) {
                    float4 o;
                    o.x = fmaxf(acc[i][0] + bb.x, 0.f);
                    o.y = fmaxf(acc[i][1] + bb.y, 0.f);
                    o.z = fmaxf(acc[i][2] + bb.z, 0.f);
                    o.w = fmaxf(acc[i][3] + bb.w, 0.f);
                    *reinterpret_cast<float4*>(&sE[(r0 + i) * 128 + c0]) = o;
                }
            }
            __syncthreads();

            // (c) post-process
            if (type < 2) {
                {   // e2 = e @ M (128 -> 32): one row + 4 cols per thread
                    const int r = tid >> 3, cq = tid & 7;
                    if (r < valid) {
                        const int gr = rt + r;
                        const int b = gr / npb, node = nodeb + (gr - b * npb);
                        float4 a4 = make_float4(0.f, 0.f, 0.f, 0.f);
                        const float4* M4 = reinterpret_cast<const float4*>(Mg) + cq;
                        const float* Er = &sE[r * 128];
#pragma unroll 4
                        for (int k = 0; k < 128; ++k) {
                            const float av = Er[k];
                            const float4 w4 = M4[k * 8];
                            a4.x += av * w4.x; a4.y += av * w4.y;
                            a4.z += av * w4.z; a4.w += av * w4.w;
                        }
                        *(reinterpret_cast<float4*>(&sE2[b * 960 + node * 32]) + cq) = a4;
                    }
                }
                if (tid < 128) {   // per-batch sums of e
                    const int c = tid;
                    int r = 0;
                    while (r < valid) {
                        const int gr = rt + r;
                        const int b = gr / npb;
                        const int rend = min(valid, r + (npb - (gr - b * npb)));
                        float s = 0.f;
                        for (int rr = r; rr < rend; ++rr) s += sE[rr * 128 + c];
                        sESS[b * 384 + sumoff + c] += s;
                        r = rend;
                    }
                }
            } else {
                for (int i = tid; i < BT * 128; i += NT) {
                    const int b = i >> 7, c = i & 127;
                    sESS[b * 384 + c] = sE[b * 128 + c];   // er
                }
            }
            __syncthreads();
        }
    }

    // (d)+(e) conv1 commons + per-node relu sums -> sVEC = [sh2|so2|r1]
    if (tid < 256) {
        const int b = tid >> 5, c0 = tid & 31;
        float a0 = g_Gb[c0], a1 = g_Gb[c0 + 32], a2 = g_Gb[c0 + 64];
        const float* in = &sESS[b * 384];
#pragma unroll 4
        for (int k = 0; k < 384; ++k) {
            const float av = in[k];
            a0 += av * g_G[k * 96 + c0];
            a1 += av * g_G[k * 96 + c0 + 32];
            a2 += av * g_G[k * 96 + c0 + 64];
        }
        float sh2 = 0.f, so2 = 0.f;
        const float* e2b = &sE2[b * 960];
#pragma unroll
        for (int n = 0; n < 20; ++n) sh2 += fmaxf(a0 + e2b[n * 32 + c0], 0.f);
#pragma unroll
        for (int n = 0; n < 10; ++n) so2 += fmaxf(a1 + e2b[(20 + n) * 32 + c0], 0.f);
        sVEC[b * 96 + c0]      = sh2;
        sVEC[b * 96 + 32 + c0] = so2;
        sVEC[b * 96 + 64 + c0] = fmaxf(a2, 0.f);
    }
    __syncthreads();

    // (f) hr = relu([sh2|so2|r1] @ G2 + b2) -> reuse sE as sHR (8x128)
    if (tid < 256) {
        const int b = tid >> 5, cg = tid & 31;
        float a[4];
#pragma unroll
        for (int j = 0; j < 4; ++j) a[j] = g_b2[cg + 32 * j];
        const float* in = &sVEC[b * 96];
#pragma unroll 4
        for (int k = 0; k < 96; ++k) {
            const float av = in[k];
#pragma unroll
            for (int j = 0; j < 4; ++j) a[j] += av * g_G2[k * 128 + cg + 32 * j];
        }
#pragma unroll
        for (int j = 0; j < 4; ++j)
            sE[b * 128 + cg + 32 * j] = fmaxf(a[j], 0.f);
    }
    __syncthreads();

    // ---- value MLP, fused ----
    // P = relu(HR @ vW0 + b0): 8x256 -> reuse sH1
    {
        const int col = tid & 255, bp = tid >> 8;  // bp in {0,1}: 4 batches each
        float a[4];
        const float bias = vb0[col];
#pragma unroll
        for (int b4 = 0; b4 < 4; ++b4) a[b4] = bias;
#pragma unroll 4
        for (int k = 0; k < 128; ++k) {
            const float w = vW0[k * 256 + col];
#pragma unroll
            for (int b4 = 0; b4 < 4; ++b4)
                a[b4] += sE[(bp * 4 + b4) * 128 + k] * w;
        }
#pragma unroll
        for (int b4 = 0; b4 < 4; ++b4)
            sH1[(bp * 4 + b4) * 256 + col] = fmaxf(a[b4], 0.f);
    }
    __syncthreads();

    // Q = relu(P @ vW1 + b1): 8x128 -> reuse sE2
    {
        const int col = tid & 127, g = tid >> 7;   // g in 0..3: 2 batches each
        float a0 = vb1[col], a1 = a0;
#pragma unroll 4
        for (int k = 0; k < 256; ++k) {
            const float w = vW1[k * 128 + col];
            a0 += sH1[(g * 2 + 0) * 256 + k] * w;
            a1 += sH1[(g * 2 + 1) * 256 + k] * w;
        }
        sE2[(g * 2 + 0) * 128 + col] = fmaxf(a0, 0.f);
        sE2[(g * 2 + 1) * 128 + col] = fmaxf(a1, 0.f);
    }
    __syncthreads();

    // v = Q @ vW2 + b2: one warp per batch
    if (tid < 256) {
        const int b = tid >> 5, l = tid & 31;
        float s = 0.f;
#pragma unroll
        for (int k = l; k < 128; k += 32) s += sE2[b * 128 + k] * vW2[k];
#pragma unroll
        for (int off = 16; off > 0; off >>= 1)
            s += __shfl_down_sync(0xffffffffu, s, off);
        if (l == 0) out[b0 + b] = s + vb2[0];
    }
}

// ============================================================
extern "C" void kernel_launch(void* const* d_in, const int* in_sizes, int n_in,
                              void* d_out, int out_size) {
    const float* state   = (const float*)d_in[0];
    const float* wrW0    = (const float*)d_in[2];
    const float* wrb0    = (const float*)d_in[3];
    const float* wrW1    = (const float*)d_in[4];
    const float* wrb1    = (const float*)d_in[5];
    const float* whW0    = (const float*)d_in[6];
    const float* whb0    = (const float*)d_in[7];
    const float* whW1    = (const float*)d_in[8];
    const float* whb1    = (const float*)d_in[9];
    const float* woW0    = (const float*)d_in[10];
    const float* wob0    = (const float*)d_in[11];
    const float* woW1    = (const float*)d_in[12];
    const float* wob1    = (const float*)d_in[13];
    const float* c1_relW = (const float*)d_in[14];
    const float* c1_relb = (const float*)d_in[15];
    const float* c1_rootW= (const float*)d_in[16];
    const float* c2_relW = (const float*)d_in[17];
    const float* c2_relb = (const float*)d_in[18];
    const float* c2_rootW= (const float*)d_in[19];
    const float* vW0     = (const float*)d_in[20];
    const float* vb0     = (const float*)d_in[21];
    const float* vW1     = (const float*)d_in[22];
    const float* vb1     = (const float*)d_in[23];
    const float* vW2     = (const float*)d_in[24];
    const float* vb2     = (const float*)d_in[25];
    float* out = (float*)d_out;

    cudaFuncSetAttribute(main_kernel, cudaFuncAttributeMaxDynamicSharedMemorySize,
                         MAIN_SMEM_FLOATS * 4);

    prep_kernel<<<64, 256>>>(c1_relW, c1_relb, c1_rootW, c2_relW, c2_relb, c2_rootW);

    main_kernel<<<BATCH / BT, NT, MAIN_SMEM_FLOATS * 4>>>(
        state, wrW0, wrb0, wrW1, wrb1, whW0, whb0, whW1, whb1,
        woW0, wob0, woW1, wob1,
        vW0, vb0, vW1, vb1, vW2, vb2, out);
}

// round 5
// speedup vs baseline: 1.6598x; 1.2573x over previous
#include <cuda_runtime.h>

#define BATCH 8192
#define BT 16           // batches per block
#define NT 512          // threads per block
#define SES 132         // sE row stride (pad: 128 -> 132 kills 4-way bank conflict)

// ---- device scratch (no allocations allowed) ----
__device__ __align__(16) float g_Mh[128 * 32];
__device__ __align__(16) float g_Mo[128 * 32];
__device__ __align__(16) float g_G[384 * 96];     // [er|sh|so] -> [common_h|common_o|pre_r]
__device__ __align__(16) float g_Gb[96];
__device__ __align__(16) float g_G2[96 * 128];    // [sh2|so2|r1] -> hr
__device__ __align__(16) float g_b2[128];

// ============================================================
// Kernel P: fold conv weights
// ============================================================
__global__ void prep_kernel(const float* __restrict__ c1_relW,
                            const float* __restrict__ c1_relb,
                            const float* __restrict__ c1_rootW,
                            const float* __restrict__ c2_relW,
                            const float* __restrict__ c2_relb,
                            const float* __restrict__ c2_rootW) {
    int tid = blockIdx.x * blockDim.x + threadIdx.x;
    int nth = gridDim.x * blockDim.x;

    for (int i = tid; i < 128 * 32; i += nth) {
        g_Mh[i] = c1_rootW[0 * 4096 + i] + c1_rootW[4 * 4096 + i] +
                  c1_rootW[6 * 4096 + i] - c1_relW[6 * 4096 + i];
        g_Mo[i] = c1_rootW[3 * 4096 + i] + c1_rootW[5 * 4096 + i] +
                  c1_rootW[7 * 4096 + i] - c1_relW[7 * 4096 + i];
    }
    for (int i = tid; i < 384 * 96; i += nth) {
        int k = i / 96, c = i % 96;
        int grp = c / 32, cc = c % 32;
        int seg = k / 128, kk = k % 128;
        int idx = kk * 32 + cc;
        float v;
        if (seg == 0) {          // er
            if (grp == 0)      v = c1_relW[0 * 4096 + idx];
            else if (grp == 1) v = c1_relW[3 * 4096 + idx];
            else               v = c1_rootW[1 * 4096 + idx] + c1_rootW[2 * 4096 + idx];
        } else if (seg == 1) {   // sh
            if (grp == 0)      v = c1_relW[6 * 4096 + idx];
            else if (grp == 1) v = c1_relW[5 * 4096 + idx];
            else               v = c1_relW[1 * 4096 + idx];
        } else {                 // so
            if (grp == 0)      v = c1_relW[4 * 4096 + idx];
            else if (grp == 1) v = c1_relW[7 * 4096 + idx];
            else               v = c1_relW[2 * 4096 + idx];
        }
        g_G[i] = v;
    }
    for (int c = tid; c < 96; c += nth) {
        int grp = c / 32, cc = c % 32;
        float v;
        if (grp == 0)      v = c1_relb[0 * 32 + cc] + c1_relb[4 * 32 + cc] + c1_relb[6 * 32 + cc];
        else if (grp == 1) v = c1_relb[3 * 32 + cc] + c1_relb[5 * 32 + cc] + c1_relb[7 * 32 + cc];
        else               v = c1_relb[1 * 32 + cc] + c1_relb[2 * 32 + cc];
        g_Gb[c] = v;
    }
    for (int i = tid; i < 96 * 128; i += nth) {
        int k = i / 128, c = i % 128;
        float v;
        if (k < 32)      v = c2_relW[1 * 4096 + k * 128 + c];
        else if (k < 64) v = c2_relW[2 * 4096 + (k - 32) * 128 + c];
        else             v = c2_rootW[1 * 4096 + (k - 64) * 128 + c] +
                             c2_rootW[2 * 4096 + (k - 64) * 128 + c];
        g_G2[i] = v;
    }
    for (int c = tid; c < 128; c += nth)
        g_b2[c] = c2_relb[1 * 128 + c] + c2_relb[2 * 128 + c];
}

// ============================================================
// Kernel M: fused embeddings + convs + value MLP
// ============================================================
// smem (floats): weights 5120 + biases 1152 + sX 3456 + sH1 8192 +
//                sE 64*132=8448 + sE2 15360 + sESS 6144 + sVEC 1536 = 49408
#define MAIN_SMEM_FLOATS 49408   // 197632 bytes

__global__ void __launch_bounds__(NT, 1) main_kernel(
    const float* __restrict__ state,
    const float* __restrict__ wrW0, const float* __restrict__ wrb0,
    const float* __restrict__ wrW1, const float* __restrict__ wrb1,
    const float* __restrict__ whW0, const float* __restrict__ whb0,
    const float* __restrict__ whW1, const float* __restrict__ whb1,
    const float* __restrict__ woW0, const float* __restrict__ wob0,
    const float* __restrict__ woW1, const float* __restrict__ wob1,
    const float* __restrict__ vW0, const float* __restrict__ vb0,
    const float* __restrict__ vW1, const float* __restrict__ vb1,
    const float* __restrict__ vW2, const float* __restrict__ vb2,
    float* __restrict__ out) {
    extern __shared__ float sm[];
    float* sW0h = sm;                  // 7x256
    float* sW0o = sW0h + 1792;
    float* sW0r = sW0o + 1792;         // 6x256
    float* sb0h = sW0r + 1536;
    float* sb0o = sb0h + 256;
    float* sb0r = sb0o + 256;
    float* sb1h = sb0r + 256;
    float* sb1o = sb1h + 128;
    float* sb1r = sb1o + 128;
    float* sXh  = sb1r + 128;          // 16 x 20 x 7
    float* sXo  = sXh + BT * 140;      // 16 x 10 x 7
    float* sXr  = sXo + BT * 70;       // 16 x 6
    float* sH1  = sXr + BT * 6;        // 64 x 128 (K-half tile)
    float* sE   = sH1 + 8192;          // 64 x 132 (padded)
    float* sE2  = sE + 64 * SES;       // 16 x 30 x 32
    float* sESS = sE2 + BT * 960;      // 16 x 384  [er|sh|so]
    float* sVEC = sESS + BT * 384;     // 16 x 96

    const int tid = threadIdx.x;
    const int b0 = blockIdx.x * BT;
    const int lane = tid & 31, warp = tid >> 5;

    // ---- stage weights + inputs ----
    for (int i = tid; i < 1792; i += NT) { sW0h[i] = whW0[i]; sW0o[i] = woW0[i]; }
    for (int i = tid; i < 1536; i += NT) sW0r[i] = wrW0[i];
    if (tid < 256) { sb0h[tid] = whb0[tid]; sb0o[tid] = wob0[tid]; sb0r[tid] = wrb0[tid]; }
    else if (tid < 384) {
        int c = tid - 256;
        sb1h[c] = whb1[c]; sb1o[c] = wob1[c]; sb1r[c] = wrb1[c];
    }
    for (int i = tid; i < BT * 140; i += NT) {
        int b = i / 140, r = i % 140, nl = r / 7, f = r % 7;
        sXh[i] = state[(b0 + b) * 390 + nl * 13 + 6 + f];
    }
    for (int i = tid; i < BT * 70; i += NT) {
        int b = i / 70, r = i % 70, nl = r / 7, f = r % 7;
        sXo[i] = state[(b0 + b) * 390 + (20 + nl) * 13 + 6 + f];
    }
    if (tid < BT * 6) {
        int b = tid / 6, f = tid % 6;
        sXr[tid] = state[(b0 + b) * 390 + f];
    }
    for (int i = tid; i < BT * 384; i += NT) sESS[i] = 0.f;
    __syncthreads();

    // ---- human/other embeddings + conv1 per-node terms (tiled GEMM) ----
#pragma unroll
    for (int type = 0; type < 2; ++type) {
        const int npb     = (type == 0) ? 20 : 10;
        const int nodeb   = (type == 1) ? 20 : 0;
        const int xstride = (type == 0) ? 140 : 70;
        const float* sW0  = (type == 0) ? sW0h : sW0o;
        const float* sb0v = (type == 0) ? sb0h : sb0o;
        const float* sb1v = (type == 0) ? sb1h : sb1o;
        const float* W1g  = (type == 0) ? whW1 : woW1;
        const float* Mg   = (type == 0) ? g_Mh : g_Mo;
        const float* sXt  = (type == 0) ? sXh : sXo;
        const int nrows   = BT * npb;
        const int sumoff  = (type == 0) ? 128 : 256;

        for (int rt = 0; rt < nrows; rt += 64) {
            const int valid = min(64, nrows - rt);
            float acc[4][4];
#pragma unroll
            for (int i = 0; i < 4; ++i)
#pragma unroll
                for (int j = 0; j < 4; ++j) acc[i][j] = 0.f;

            for (int half = 0; half < 2; ++half) {
                // (a) layer1: h1 = relu(x @ W0 + b0), 64 rows x 128 cols (K-half)
                {
                    const int colg = tid & 127, rg = tid >> 7;
                    float w0r[7];
#pragma unroll
                    for (int k = 0; k < 7; ++k)
                        w0r[k] = sW0[k * 256 + half * 128 + colg];
                    const float bias = sb0v[half * 128 + colg];
#pragma unroll 4
                    for (int rr = 0; rr < 16; ++rr) {
                        int r = rg * 16 + rr;
                        int gr = rt + r; if (gr >= nrows) gr = nrows - 1;
                        const int b = gr / npb, nl = gr - b * npb;
                        const float* x = &sXt[b * xstride + nl * 7];
                        float a = bias;
#pragma unroll
                        for (int k = 0; k < 7; ++k) a += x[k] * w0r[k];
                        sH1[r * 128 + colg] = fmaxf(a, 0.f);
                    }
                }
                __syncthreads();

                // (b) layer2 partial: acc += h1_half @ W1_half  (64x128, K=128)
                {
                    const int r0 = warp * 4, c0 = lane * 4;
                    const float* Wp = W1g + half * 128 * 128 + c0;
#pragma unroll 2
                    for (int k = 0; k < 128; k += 4) {
                        float a[4][4];
#pragma unroll
                        for (int i = 0; i < 4; ++i) {
                            float4 t = *reinterpret_cast<const float4*>(&sH1[(r0 + i) * 128 + k]);
                            a[i][0] = t.x; a[i][1] = t.y; a[i][2] = t.z; a[i][3] = t.w;
                        }
#pragma unroll
                        for (int kk = 0; kk < 4; ++kk) {
                            float4 w = *reinterpret_cast<const float4*>(&Wp[(k + kk) * 128]);
#pragma unroll
                            for (int i = 0; i < 4; ++i) {
                                acc[i][0] += a[i][kk] * w.x;
                                acc[i][1] += a[i][kk] * w.y;
                                acc[i][2] += a[i][kk] * w.z;
                                acc[i][3] += a[i][kk] * w.w;
                            }
                        }
                    }
                }
                __syncthreads();   // sH1 reused next half
            }

            // (b-finish) bias + relu -> sE (stride SES)
            {
                const int r0 = warp * 4, c0 = lane * 4;
                float4 bb = *reinterpret_cast<const float4*>(&sb1v[c0]);
#pragma unroll
                for (int i = 0; i < 4; ++i) {
                    float4 o;
                    o.x = fmaxf(acc[i][0] + bb.x, 0.f);
                    o.y = fmaxf(acc[i][1] + bb.y, 0.f);
                    o.z = fmaxf(acc[i][2] + bb.z, 0.f);
                    o.w = fmaxf(acc[i][3] + bb.w, 0.f);
                    *reinterpret_cast<float4*>(&sE[(r0 + i) * SES + c0]) = o;
                }
            }
            __syncthreads();

            // (c) e2 = e @ M (128 -> 32) + per-batch sums
            {
                const int r = tid >> 3, cq = tid & 7;
                if (r < valid) {
                    const int gr = rt + r;
                    const int b = gr / npb, node = nodeb + (gr - b * npb);
                    float4 a4 = make_float4(0.f, 0.f, 0.f, 0.f);
                    const float4* M4 = reinterpret_cast<const float4*>(Mg) + cq;
                    const float* Er = &sE[r * SES];
#pragma unroll 4
                    for (int k = 0; k < 128; ++k) {
                        const float av = Er[k];
                        const float4 w4 = M4[k * 8];
                        a4.x += av * w4.x; a4.y += av * w4.y;
                        a4.z += av * w4.z; a4.w += av * w4.w;
                    }
                    *(reinterpret_cast<float4*>(&sE2[b * 960 + node * 32]) + cq) = a4;
                }
            }
            if (tid < 128) {
                const int c = tid;
                int r = 0;
                while (r < valid) {
                    const int gr = rt + r;
                    const int b = gr / npb;
                    const int rend = min(valid, r + (npb - (gr - b * npb)));
                    float s = 0.f;
                    for (int rr = r; rr < rend; ++rr) s += sE[rr * SES + c];
                    sESS[b * 384 + sumoff + c] += s;
                    r = rend;
                }
            }
            __syncthreads();
        }
    }

    // ---- root embedding: 16 rows, direct path (no padded tile) ----
    {
        // h1 = relu(xr @ wrW0 + b0): 16x256 -> sH1 (stride 256)
        const int col = tid & 255, grp = tid >> 8;   // grp 0..1 -> 8 rows each
        float w0r[6];
#pragma unroll
        for (int k = 0; k < 6; ++k) w0r[k] = sW0r[k * 256 + col];
        const float bias = sb0r[col];
#pragma unroll
        for (int rr = 0; rr < 8; ++rr) {
            const int b = grp * 8 + rr;
            const float* x = &sXr[b * 6];
            float a = bias;
#pragma unroll
            for (int k = 0; k < 6; ++k) a += x[k] * w0r[k];
            sH1[b * 256 + col] = fmaxf(a, 0.f);
        }
    }
    __syncthreads();
    {
        // er = relu(h1 @ wrW1 + b1): 16x128 -> sESS[b*384 + 0..127]
        const int col = tid & 127, g = tid >> 7;     // g 0..3 -> 4 rows each
        float a[4];
        const float bias = sb1r[col];
#pragma unroll
        for (int i = 0; i < 4; ++i) a[i] = bias;
#pragma unroll 4
        for (int k = 0; k < 256; ++k) {
            const float w = wrW1[k * 128 + col];
#pragma unroll
            for (int i = 0; i < 4; ++i) a[i] += sH1[(g * 4 + i) * 256 + k] * w;
        }
#pragma unroll
        for (int i = 0; i < 4; ++i)
            sESS[(g * 4 + i) * 384 + col] = fmaxf(a[i], 0.f);
    }
    __syncthreads();

    // (d)+(e) conv1 commons + per-node relu sums -> sVEC (2 batches per thread)
    if (tid < 256) {
        const int bp = tid >> 5, c0 = tid & 31;
        const int ba = bp * 2, bb = ba + 1;
        float a0a = g_Gb[c0], a1a = g_Gb[c0 + 32], a2a = g_Gb[c0 + 64];
        float a0b = a0a, a1b = a1a, a2b = a2a;
        const float* ina = &sESS[ba * 384];
        const float* inb = &sESS[bb * 384];
#pragma unroll 4
        for (int k = 0; k < 384; ++k) {
            const float g0 = g_G[k * 96 + c0];
            const float g1 = g_G[k * 96 + c0 + 32];
            const float g2 = g_G[k * 96 + c0 + 64];
            const float va = ina[k], vb = inb[k];
            a0a += va * g0; a1a += va * g1; a2a += va * g2;
            a0b += vb * g0; a1b += vb * g1; a2b += vb * g2;
        }
        const float* e2a = &sE2[ba * 960];
        const float* e2b = &sE2[bb * 960];
        float sha = 0.f, soa = 0.f, shb = 0.f, sob = 0.f;
#pragma unroll
        for (int n = 0; n < 20; ++n) {
            sha += fmaxf(a0a + e2a[n * 32 + c0], 0.f);
            shb += fmaxf(a0b + e2b[n * 32 + c0], 0.f);
        }
#pragma unroll
        for (int n = 0; n < 10; ++n) {
            soa += fmaxf(a1a + e2a[(20 + n) * 32 + c0], 0.f);
            sob += fmaxf(a1b + e2b[(20 + n) * 32 + c0], 0.f);
        }
        sVEC[ba * 96 + c0]      = sha;
        sVEC[ba * 96 + 32 + c0] = soa;
        sVEC[ba * 96 + 64 + c0] = fmaxf(a2a, 0.f);
        sVEC[bb * 96 + c0]      = shb;
        sVEC[bb * 96 + 32 + c0] = sob;
        sVEC[bb * 96 + 64 + c0] = fmaxf(a2b, 0.f);
    }
    __syncthreads();

    // (f) hr = relu([sh2|so2|r1] @ G2 + b2) -> reuse sE as HR (16x128)
    {
        const int b = tid >> 5, cg = tid & 31;
        float a[4];
#pragma unroll
        for (int j = 0; j < 4; ++j) a[j] = g_b2[cg + 32 * j];
        const float* in = &sVEC[b * 96];
#pragma unroll 4
        for (int k = 0; k < 96; ++k) {
            const float av = in[k];
#pragma unroll
            for (int j = 0; j < 4; ++j) a[j] += av * g_G2[k * 128 + cg + 32 * j];
        }
#pragma unroll
        for (int j = 0; j < 4; ++j)
            sE[b * 128 + cg + 32 * j] = fmaxf(a[j], 0.f);
    }
    __syncthreads();

    // ---- value MLP ----
    // P = relu(HR @ vW0 + b0): 16x256 -> reuse sH1
    {
        const int col = tid & 255, bp = tid >> 8;    // bp 0..1 -> 8 batches each
        float a[8];
        const float bias = vb0[col];
#pragma unroll
        for (int i = 0; i < 8; ++i) a[i] = bias;
#pragma unroll 4
        for (int k = 0; k < 128; ++k) {
            const float w = vW0[k * 256 + col];
#pragma unroll
            for (int i = 0; i < 8; ++i)
                a[i] += sE[(bp * 8 + i) * 128 + k] * w;
        }
#pragma unroll
        for (int i = 0; i < 8; ++i)
            sH1[(bp * 8 + i) * 256 + col] = fmaxf(a[i], 0.f);
    }
    __syncthreads();

    // Q = relu(P @ vW1 + b1): 16x128 -> reuse sE2
    {
        const int col = tid & 127, g = tid >> 7;     // g 0..3 -> 4 batches each
        float a[4];
        const float bias = vb1[col];
#pragma unroll
        for (int i = 0; i < 4; ++i) a[i] = bias;
#pragma unroll 4
        for (int k = 0; k < 256; ++k) {
            const float w = vW1[k * 128 + col];
#pragma unroll
            for (int i = 0; i < 4; ++i) a[i] += sH1[(g * 4 + i) * 256 + k] * w;
        }
#pragma unroll
        for (int i = 0; i < 4; ++i)
            sE2[(g * 4 + i) * 128 + col] = fmaxf(a[i], 0.f);
    }
    __syncthreads();

    // v = Q @ vW2 + b2: one warp per batch (16 warps = 16 batches)
    {
        const int b = warp, l = lane;
        float s = 0.f;
#pragma unroll
        for (int k = l; k < 128; k += 32) s += sE2[b * 128 + k] * vW2[k];
#pragma unroll
        for (int off = 16; off > 0; off >>= 1)
            s += __shfl_down_sync(0xffffffffu, s, off);
        if (l == 0) out[b0 + b] = s + vb2[0];
    }
}

// ============================================================
extern "C" void kernel_launch(void* const* d_in, const int* in_sizes, int n_in,
                              void* d_out, int out_size) {
    const float* state   = (const float*)d_in[0];
    const float* wrW0    = (const float*)d_in[2];
    const float* wrb0    = (const float*)d_in[3];
    const float* wrW1    = (const float*)d_in[4];
    const float* wrb1    = (const float*)d_in[5];
    const float* whW0    = (const float*)d_in[6];
    const float* whb0    = (const float*)d_in[7];
    const float* whW1    = (const float*)d_in[8];
    const float* whb1    = (const float*)d_in[9];
    const float* woW0    = (const float*)d_in[10];
    const float* wob0    = (const float*)d_in[11];
    const float* woW1    = (const float*)d_in[12];
    const float* wob1    = (const float*)d_in[13];
    const float* c1_relW = (const float*)d_in[14];
    const float* c1_relb = (const float*)d_in[15];
    const float* c1_rootW= (const float*)d_in[16];
    const float* c2_relW = (const float*)d_in[17];
    const float* c2_relb = (const float*)d_in[18];
    const float* c2_rootW= (const float*)d_in[19];
    const float* vW0     = (const float*)d_in[20];
    const float* vb0     = (const float*)d_in[21];
    const float* vW1     = (const float*)d_in[22];
    const float* vb1     = (const float*)d_in[23];
    const float* vW2     = (const float*)d_in[24];
    const float* vb2     = (const float*)d_in[25];
    float* out = (float*)d_out;

    cudaFuncSetAttribute(main_kernel, cudaFuncAttributeMaxDynamicSharedMemorySize,
                         MAIN_SMEM_FLOATS * 4);

    prep_kernel<<<64, 256>>>(c1_relW, c1_relb, c1_rootW, c2_relW, c2_relb, c2_rootW);

    main_kernel<<<BATCH / BT, NT, MAIN_SMEM_FLOATS * 4>>>(
        state, wrW0, wrb0, wrW1, wrb1, whW0, whb0, whW1, whb1,
        woW0, wob0, woW1, wob1,
        vW0, vb0, vW1, vb1, vW2, vb2, out);
}

// round 7
// speedup vs baseline: 2.0481x; 1.2340x over previous
#include <cuda_runtime.h>

#define BATCH 8192
#define BT 16           // batches per block
#define NT 512          // threads per block
#define TILE 160        // GEMM tile rows (16 warps x 10 rows)
#define RPW 10          // rows per warp
#define KQ 16           // k-slice width for layer1 staging
#define SES 132         // sE row stride (pad kills bank conflicts)

// ---- device scratch (no allocations allowed) ----
__device__ __align__(16) float g_Mh[128 * 32];
__device__ __align__(16) float g_Mo[128 * 32];
__device__ __align__(16) float g_G[384 * 96];     // [er|sh|so] -> [common_h|common_o|pre_r]
__device__ __align__(16) float g_Gb[96];
__device__ __align__(16) float g_G2[96 * 128];    // [sh2|so2|r1] -> hr
__device__ __align__(16) float g_b2[128];

// ============================================================
// Kernel P: fold conv weights
// ============================================================
__global__ void prep_kernel(const float* __restrict__ c1_relW,
                            const float* __restrict__ c1_relb,
                            const float* __restrict__ c1_rootW,
                            const float* __restrict__ c2_relW,
                            const float* __restrict__ c2_relb,
                            const float* __restrict__ c2_rootW) {
    int tid = blockIdx.x * blockDim.x + threadIdx.x;
    int nth = gridDim.x * blockDim.x;

    for (int i = tid; i < 128 * 32; i += nth) {
        g_Mh[i] = c1_rootW[0 * 4096 + i] + c1_rootW[4 * 4096 + i] +
                  c1_rootW[6 * 4096 + i] - c1_relW[6 * 4096 + i];
        g_Mo[i] = c1_rootW[3 * 4096 + i] + c1_rootW[5 * 4096 + i] +
                  c1_rootW[7 * 4096 + i] - c1_relW[7 * 4096 + i];
    }
    for (int i = tid; i < 384 * 96; i += nth) {
        int k = i / 96, c = i % 96;
        int grp = c / 32, cc = c % 32;
        int seg = k / 128, kk = k % 128;
        int idx = kk * 32 + cc;
        float v;
        if (seg == 0) {          // er
            if (grp == 0)      v = c1_relW[0 * 4096 + idx];
            else if (grp == 1) v = c1_relW[3 * 4096 + idx];
            else               v = c1_rootW[1 * 4096 + idx] + c1_rootW[2 * 4096 + idx];
        } else if (seg == 1) {   // sh
            if (grp == 0)      v = c1_relW[6 * 4096 + idx];
            else if (grp == 1) v = c1_relW[5 * 4096 + idx];
            else               v = c1_relW[1 * 4096 + idx];
        } else {                 // so
            if (grp == 0)      v = c1_relW[4 * 4096 + idx];
            else if (grp == 1) v = c1_relW[7 * 4096 + idx];
            else               v = c1_relW[2 * 4096 + idx];
        }
        g_G[i] = v;
    }
    for (int c = tid; c < 96; c += nth) {
        int grp = c / 32, cc = c % 32;
        float v;
        if (grp == 0)      v = c1_relb[0 * 32 + cc] + c1_relb[4 * 32 + cc] + c1_relb[6 * 32 + cc];
        else if (grp == 1) v = c1_relb[3 * 32 + cc] + c1_relb[5 * 32 + cc] + c1_relb[7 * 32 + cc];
        else               v = c1_relb[1 * 32 + cc] + c1_relb[2 * 32 + cc];
        g_Gb[c] = v;
    }
    for (int i = tid; i < 96 * 128; i += nth) {
        int k = i / 128, c = i % 128;
        float v;
        if (k < 32)      v = c2_relW[1 * 4096 + k * 128 + c];
        else if (k < 64) v = c2_relW[2 * 4096 + (k - 32) * 128 + c];
        else             v = c2_rootW[1 * 4096 + (k - 64) * 128 + c] +
                             c2_rootW[2 * 4096 + (k - 64) * 128 + c];
        g_G2[i] = v;
    }
    for (int c = tid; c < 128; c += nth)
        g_b2[c] = c2_relb[1 * 128 + c] + c2_relb[2 * 128 + c];
}

// ============================================================
// Kernel M: fused embeddings + convs + value MLP
// ============================================================
// smem (floats): weights 6272 | sX 3456 | sH1 2560 | sE 21120 |
//                sE2 15360 | sESS 6144 | sVEC 1536  = 56448 (225792 B)
#define MAIN_SMEM_FLOATS 56448

__global__ void __launch_bounds__(NT, 1) main_kernel(
    const float* __restrict__ state,
    const float* __restrict__ wrW0, const float* __restrict__ wrb0,
    const float* __restrict__ wrW1, const float* __restrict__ wrb1,
    const float* __restrict__ whW0, const float* __restrict__ whb0,
    const float* __restrict__ whW1, const float* __restrict__ whb1,
    const float* __restrict__ woW0, const float* __restrict__ wob0,
    const float* __restrict__ woW1, const float* __restrict__ wob1,
    const float* __restrict__ vW0, const float* __restrict__ vb0,
    const float* __restrict__ vW1, const float* __restrict__ vb1,
    const float* __restrict__ vW2, const float* __restrict__ vb2,
    float* __restrict__ out) {
    extern __shared__ float sm[];
    float* sW0h = sm;                  // 7x256
    float* sW0o = sW0h + 1792;
    float* sW0r = sW0o + 1792;         // 6x256
    float* sb0h = sW0r + 1536;
    float* sb0o = sb0h + 256;
    float* sb0r = sb0o + 256;
    float* sb1h = sb0r + 256;
    float* sb1o = sb1h + 128;
    float* sb1r = sb1o + 128;
    float* sXh  = sb1r + 128;          // 16 x 20 x 7
    float* sXo  = sXh + BT * 140;      // 16 x 10 x 7
    float* sXr  = sXo + BT * 70;       // 16 x 6
    float* sH1  = sXr + BT * 6;        // 160 x 16 (k-slice)
    float* sE   = sH1 + TILE * KQ;     // 160 x 132
    float* sE2  = sE + TILE * SES;     // 16 x 30 x 32
    float* sESS = sE2 + BT * 960;      // 16 x 384  [er|sh|so]
    float* sVEC = sESS + BT * 384;     // 16 x 96

    const int tid = threadIdx.x;
    const int b0 = blockIdx.x * BT;
    const int lane = tid & 31, warp = tid >> 5;

    // ---- stage weights + inputs ----
    for (int i = tid; i < 1792; i += NT) { sW0h[i] = whW0[i]; sW0o[i] = woW0[i]; }
    for (int i = tid; i < 1536; i += NT) sW0r[i] = wrW0[i];
    if (tid < 256) { sb0h[tid] = whb0[tid]; sb0o[tid] = wob0[tid]; sb0r[tid] = wrb0[tid]; }
    else if (tid < 384) {
        int c = tid - 256;
        sb1h[c] = whb1[c]; sb1o[c] = wob1[c]; sb1r[c] = wrb1[c];
    }
    for (int i = tid; i < BT * 140; i += NT) {
        int b = i / 140, r = i % 140, nl = r / 7, f = r % 7;
        sXh[i] = state[(b0 + b) * 390 + nl * 13 + 6 + f];
    }
    for (int i = tid; i < BT * 70; i += NT) {
        int b = i / 70, r = i % 70, nl = r / 7, f = r % 7;
        sXo[i] = state[(b0 + b) * 390 + (20 + nl) * 13 + 6 + f];
    }
    if (tid < BT * 6) {
        int b = tid / 6, f = tid % 6;
        sXr[tid] = state[(b0 + b) * 390 + f];
    }
    __syncthreads();

    // ---- human/other embeddings + conv1 per-node terms ----
#pragma unroll
    for (int type = 0; type < 2; ++type) {
        const int npb     = (type == 0) ? 20 : 10;
        const int nodeb   = (type == 1) ? 20 : 0;
        const int xstride = (type == 0) ? 140 : 70;
        const float* sW0  = (type == 0) ? sW0h : sW0o;
        const float* sb0v = (type == 0) ? sb0h : sb0o;
        const float* sb1v = (type == 0) ? sb1h : sb1o;
        const float* W1g  = (type == 0) ? whW1 : woW1;
        const float* Mg   = (type == 0) ? g_Mh : g_Mo;
        const float* sXt  = (type == 0) ? sXh : sXo;
        const int nrows   = BT * npb;     // 320 or 160: exact multiples of TILE
        const int sumoff  = (type == 0) ? 128 : 256;

        for (int rt = 0; rt < nrows; rt += TILE) {
            float acc[RPW][4];
#pragma unroll
            for (int i = 0; i < RPW; ++i)
#pragma unroll
                for (int j = 0; j < 4; ++j) acc[i][j] = 0.f;

            for (int kq = 0; kq < 256; kq += KQ) {
                // (a) layer1 k-slice: h1[160][16] = relu(x @ W0[:, kq:kq+16] + b0)
                {
                    const int colq = tid & 15;       // 0..15
                    const int rowg = tid >> 4;       // 0..31 -> 5 rows each
                    float w0r[7];
#pragma unroll
                    for (int k = 0; k < 7; ++k)
                        w0r[k] = sW0[k * 256 + kq + colq];
                    const float bias = sb0v[kq + colq];
#pragma unroll
                    for (int rr = 0; rr < 5; ++rr) {
                        const int r = rowg * 5 + rr;
                        const int gr = rt + r;
                        const int b = gr / npb, nl = gr - b * npb;
                        const float* x = &sXt[b * xstride + nl * 7];
                        float a = bias;
#pragma unroll
                        for (int k = 0; k < 7; ++k) a += x[k] * w0r[k];
                        sH1[r * KQ + colq] = fmaxf(a, 0.f);
                    }
                }
                __syncthreads();

                // (b) GEMM partial: acc += h1_slice @ W1[kq:kq+16, :]
                {
                    const int r0 = warp * RPW, c0 = lane * 4;
                    const float* Wp = W1g + c0;
#pragma unroll
                    for (int k = 0; k < KQ; k += 4) {
                        float a[RPW][4];
#pragma unroll
                        for (int i = 0; i < RPW; ++i) {
                            float4 t = *reinterpret_cast<const float4*>(&sH1[(r0 + i) * KQ + k]);
                            a[i][0] = t.x; a[i][1] = t.y; a[i][2] = t.z; a[i][3] = t.w;
                        }
#pragma unroll
                        for (int kk = 0; kk < 4; ++kk) {
                            float4 w = *reinterpret_cast<const float4*>(&Wp[(kq + k + kk) * 128]);
#pragma unroll
                            for (int i = 0; i < RPW; ++i) {
                                acc[i][0] += a[i][kk] * w.x;
                                acc[i][1] += a[i][kk] * w.y;
                                acc[i][2] += a[i][kk] * w.z;
                                acc[i][3] += a[i][kk] * w.w;
                            }
                        }
                    }
                }
                __syncthreads();   // sH1 reused next slice
            }

            // (b-finish) bias + relu -> sE
            {
                const int r0 = warp * RPW, c0 = lane * 4;
                float4 bb = *reinterpret_cast<const float4*>(&sb1v[c0]);
#pragma unroll
                for (int i = 0; i < RPW; ++i) {
                    float4 o;
                    o.x = fmaxf(acc[i][0] + bb.x, 0.f);
                    o.y = fmaxf(acc[i][1] + bb.y, 0.f);
                    o.z = fmaxf(acc[i][2] + bb.z, 0.f);
                    o.w = fmaxf(acc[i][3] + bb.w, 0.f);
                    *reinterpret_cast<float4*>(&sE[(r0 + i) * SES + c0]) = o;
                }
            }
            __syncthreads();

            // (c1) per-batch sums: 512 threads, 40-row chunks (batch-aligned)
            {
                const int c = tid & 127, chunk = tid >> 7;   // 4 chunks x 40 rows
                const int rbase = chunk * 40;
                int r = 0;
                while (r < 40) {
                    float s = 0.f;
#pragma unroll
                    for (int rr = 0; rr < 10; ++rr)          // npb multiple of 10
                        s += sE[(rbase + r + rr) * SES + c];
                    if (npb == 10) {
                        const int b = (rt + rbase + r) / 10;
                        sESS[b * 384 + sumoff + c] = s;
                        r += 10;
                    } else {
                        float s2 = 0.f;
#pragma unroll
                        for (int rr = 10; rr < 20; ++rr)
                            s2 += sE[(rbase + r + rr) * SES + c];
                        const int b = (rt + rbase + r) / 20;
                        sESS[b * 384 + sumoff + c] = s + s2;
                        r += 20;
                    }
                }
            }

            // (c2) e2 = e @ M (128 -> 32): 2-3 rows per thread, M reused
            {
                const int cq = tid & 7, rslot = tid >> 3;    // 64 row-slots
                const int nr = (rslot < 32) ? 3 : 2;
                float4 a0 = make_float4(0.f, 0.f, 0.f, 0.f), a1 = a0, a2 = a0;
                const float* E0 = &sE[rslot * SES];
                const float* E1 = &sE[(rslot + 64) * SES];
                const float* E2p = &sE[(rslot + 128) * SES];
                const float4* M4 = reinterpret_cast<const float4*>(Mg) + cq;
#pragma unroll 4
                for (int k = 0; k < 128; ++k) {
                    const float4 w = M4[k * 8];
                    const float e0 = E0[k], e1 = E1[k];
                    a0.x += e0 * w.x; a0.y += e0 * w.y; a0.z += e0 * w.z; a0.w += e0 * w.w;
                    a1.x += e1 * w.x; a1.y += e1 * w.y; a1.z += e1 * w.z; a1.w += e1 * w.w;
                    if (nr == 3) {
                        const float e2v = E2p[k];
                        a2.x += e2v * w.x; a2.y += e2v * w.y; a2.z += e2v * w.z; a2.w += e2v * w.w;
                    }
                }
#pragma unroll
                for (int j = 0; j < 3; ++j) {
                    if (j >= nr) break;
                    const int r = rslot + j * 64;
                    const int gr = rt + r;
                    const int b = gr / npb, node = nodeb + (gr - b * npb);
                    float4 v = (j == 0) ? a0 : (j == 1) ? a1 : a2;
                    *(reinterpret_cast<float4*>(&sE2[b * 960 + node * 32]) + cq) = v;
                }
            }
            __syncthreads();
        }
    }

    // ---- root embedding: 16 rows, direct path (h1 staged in sE) ----
    {
        const int col = tid & 255, grp = tid >> 8;   // grp 0..1 -> 8 rows each
        float w0r[6];
#pragma unroll
        for (int k = 0; k < 6; ++k) w0r[k] = sW0r[k * 256 + col];
        const float bias = sb0r[col];
#pragma unroll
        for (int rr = 0; rr < 8; ++rr) {
            const int b = grp * 8 + rr;
            const float* x = &sXr[b * 6];
            float a = bias;
#pragma unroll
            for (int k = 0; k < 6; ++k) a += x[k] * w0r[k];
            sE[b * 256 + col] = fmaxf(a, 0.f);
        }
    }
    __syncthreads();
    {
        // er = relu(h1 @ wrW1 + b1): 16x128 -> sESS[b*384 + 0..127]
        const int col = tid & 127, g = tid >> 7;     // g 0..3 -> 4 rows each
        float a[4];
        const float bias = sb1r[col];
#pragma unroll
        for (int i = 0; i < 4; ++i) a[i] = bias;
#pragma unroll 4
        for (int k = 0; k < 256; ++k) {
            const float w = wrW1[k * 128 + col];
#pragma unroll
            for (int i = 0; i < 4; ++i) a[i] += sE[(g * 4 + i) * 256 + k] * w;
        }
#pragma unroll
        for (int i = 0; i < 4; ++i)
            sESS[(g * 4 + i) * 384 + col] = fmaxf(a[i], 0.f);
    }
    __syncthreads();

    // (d)+(e) conv1 commons + per-node relu sums -> sVEC (2 batches/thread)
    if (tid < 256) {
        const int bp = tid >> 5, c0 = tid & 31;
        const int ba = bp * 2, bb = ba + 1;
        float a0a = g_Gb[c0], a1a = g_Gb[c0 + 32], a2a = g_Gb[c0 + 64];
        float a0b = a0a, a1b = a1a, a2b = a2a;
        const float* ina = &sESS[ba * 384];
        const float* inb = &sESS[bb * 384];
#pragma unroll 4
        for (int k = 0; k < 384; ++k) {
            const float g0 = g_G[k * 96 + c0];
            const float g1 = g_G[k * 96 + c0 + 32];
            const float g2 = g_G[k * 96 + c0 + 64];
            const float va = ina[k], vb = inb[k];
            a0a += va * g0; a1a += va * g1; a2a += va * g2;
            a0b += vb * g0; a1b += vb * g1; a2b += vb * g2;
        }
        const float* e2a = &sE2[ba * 960];
        const float* e2b = &sE2[bb * 960];
        float sha = 0.f, soa = 0.f, shb = 0.f, sob = 0.f;
#pragma unroll
        for (int n = 0; n < 20; ++n) {
            sha += fmaxf(a0a + e2a[n * 32 + c0], 0.f);
            shb += fmaxf(a0b + e2b[n * 32 + c0], 0.f);
        }
#pragma unroll
        for (int n = 0; n < 10; ++n) {
            soa += fmaxf(a1a + e2a[(20 + n) * 32 + c0], 0.f);
            sob += fmaxf(a1b + e2b[(20 + n) * 32 + c0], 0.f);
        }
        sVEC[ba * 96 + c0]      = sha;
        sVEC[ba * 96 + 32 + c0] = soa;
        sVEC[ba * 96 + 64 + c0] = fmaxf(a2a, 0.f);
        sVEC[bb * 96 + c0]      = shb;
        sVEC[bb * 96 + 32 + c0] = sob;
        sVEC[bb * 96 + 64 + c0] = fmaxf(a2b, 0.f);
    }
    __syncthreads();

    // (f) hr = relu([sh2|so2|r1] @ G2 + b2) -> sE as HR (16x128)
    {
        const int b = tid >> 5, cg = tid & 31;
        float a[4];
#pragma unroll
        for (int j = 0; j < 4; ++j) a[j] = g_b2[cg + 32 * j];
        const float* in = &sVEC[b * 96];
#pragma unroll 4
        for (int k = 0; k < 96; ++k) {
            const float av = in[k];
#pragma unroll
            for (int j = 0; j < 4; ++j) a[j] += av * g_G2[k * 128 + cg + 32 * j];
        }
#pragma unroll
        for (int j = 0; j < 4; ++j)
            sE[b * 128 + cg + 32 * j] = fmaxf(a[j], 0.f);
    }
    __syncthreads();

    // ---- value MLP ----
    // P = relu(HR @ vW0 + b0): 16x256 -> sE2[0..4095]
    {
        const int col = tid & 255, bp = tid >> 8;    // bp 0..1 -> 8 batches each
        float a[8];
        const float bias = vb0[col];
#pragma unroll
        for (int i = 0; i < 8; ++i) a[i] = bias;
#pragma unroll 4
        for (int k = 0; k < 128; ++k) {
            const float w = vW0[k * 256 + col];
#pragma unroll
            for (int i = 0; i < 8; ++i)
                a[i] += sE[(bp * 8 + i) * 128 + k] * w;
        }
#pragma unroll
        for (int i = 0; i < 8; ++i)
            sE2[(bp * 8 + i) * 256 + col] = fmaxf(a[i], 0.f);
    }
    __syncthreads();

    // Q = relu(P @ vW1 + b1): 16x128 -> sE2[4096..6143]
    {
        const int col = tid & 127, g = tid >> 7;     // g 0..3 -> 4 batches each
        float a[4];
        const float bias = vb1[col];
#pragma unroll
        for (int i = 0; i < 4; ++i) a[i] = bias;
#pragma unroll 4
        for (int k = 0; k < 256; ++k) {
            const float w = vW1[k * 128 + col];
#pragma unroll
            for (int i = 0; i < 4; ++i) a[i] += sE2[(g * 4 + i) * 256 + k] * w;
        }
#pragma unroll
        for (int i = 0; i < 4; ++i)
            sE2[4096 + (g * 4 + i) * 128 + col] = fmaxf(a[i], 0.f);
    }
    __syncthreads();

    // v = Q @ vW2 + b2: one warp per batch (16 warps = 16 batches)
    {
        const int b = warp, l = lane;
        float s = 0.f;
#pragma unroll
        for (int k = l; k < 128; k += 32) s += sE2[4096 + b * 128 + k] * vW2[k];
#pragma unroll
        for (int off = 16; off > 0; off >>= 1)
            s += __shfl_down_sync(0xffffffffu, s, off);
        if (l == 0) out[b0 + b] = s + vb2[0];
    }
}

// ============================================================
extern "C" void kernel_launch(void* const* d_in, const int* in_sizes, int n_in,
                              void* d_out, int out_size) {
    const float* state   = (const float*)d_in[0];
    const float* wrW0    = (const float*)d_in[2];
    const float* wrb0    = (const float*)d_in[3];
    const float* wrW1    = (const float*)d_in[4];
    const float* wrb1    = (const float*)d_in[5];
    const float* whW0    = (const float*)d_in[6];
    const float* whb0    = (const float*)d_in[7];
    const float* whW1    = (const float*)d_in[8];
    const float* whb1    = (const float*)d_in[9];
    const float* woW0    = (const float*)d_in[10];
    const float* wob0    = (const float*)d_in[11];
    const float* woW1    = (const float*)d_in[12];
    const float* wob1    = (const float*)d_in[13];
    const float* c1_relW = (const float*)d_in[14];
    const float* c1_relb = (const float*)d_in[15];
    const float* c1_rootW= (const float*)d_in[16];
    const float* c2_relW = (const float*)d_in[17];
    const float* c2_relb = (const float*)d_in[18];
    const float* c2_rootW= (const float*)d_in[19];
    const float* vW0     = (const float*)d_in[20];
    const float* vb0     = (const float*)d_in[21];
    const float* vW1     = (const float*)d_in[22];
    const float* vb1     = (const float*)d_in[23];
    const float* vW2     = (const float*)d_in[24];
    const float* vb2     = (const float*)d_in[25];
    float* out = (float*)d_out;

    cudaFuncSetAttribute(main_kernel, cudaFuncAttributeMaxDynamicSharedMemorySize,
                         MAIN_SMEM_FLOATS * 4);

    prep_kernel<<<64, 256>>>(c1_relW, c1_relb, c1_rootW, c2_relW, c2_relb, c2_rootW);

    main_kernel<<<BATCH / BT, NT, MAIN_SMEM_FLOATS * 4>>>(
        state, wrW0, wrb0, wrW1, wrb1, whW0, whb0, whW1, whb1,
        woW0, wob0, woW1, wob1,
        vW0, vb0, vW1, vb1, vW2, vb2, out);
}

// round 8
// speedup vs baseline: 2.3869x; 1.1654x over previous
#include <cuda_runtime.h>

#define BATCH 8192
#define BT 8            // batches per block
#define NT 256          // threads per block
#define TILE 80         // GEMM tile rows (8 warps x 10 rows)
#define RPW 10          // rows per warp
#define KQ 16           // k-slice width for layer1 staging
#define SES 132         // sE row stride (pad kills bank conflicts)

// ---- device scratch (no allocations allowed) ----
__device__ __align__(16) float g_Mh[128 * 32];
__device__ __align__(16) float g_Mo[128 * 32];
__device__ __align__(16) float g_G[384 * 96];     // [er|sh|so] -> [common_h|common_o|pre_r]
__device__ __align__(16) float g_Gb[96];
__device__ __align__(16) float g_G2[96 * 128];    // [sh2|so2|r1] -> hr
__device__ __align__(16) float g_b2[128];

// ============================================================
// Kernel P: fold conv weights
// ============================================================
__global__ void prep_kernel(const float* __restrict__ c1_relW,
                            const float* __restrict__ c1_relb,
                            const float* __restrict__ c1_rootW,
                            const float* __restrict__ c2_relW,
                            const float* __restrict__ c2_relb,
                            const float* __restrict__ c2_rootW) {
    int tid = blockIdx.x * blockDim.x + threadIdx.x;
    int nth = gridDim.x * blockDim.x;

    for (int i = tid; i < 128 * 32; i += nth) {
        g_Mh[i] = c1_rootW[0 * 4096 + i] + c1_rootW[4 * 4096 + i] +
                  c1_rootW[6 * 4096 + i] - c1_relW[6 * 4096 + i];
        g_Mo[i] = c1_rootW[3 * 4096 + i] + c1_rootW[5 * 4096 + i] +
                  c1_rootW[7 * 4096 + i] - c1_relW[7 * 4096 + i];
    }
    for (int i = tid; i < 384 * 96; i += nth) {
        int k = i / 96, c = i % 96;
        int grp = c / 32, cc = c % 32;
        int seg = k / 128, kk = k % 128;
        int idx = kk * 32 + cc;
        float v;
        if (seg == 0) {          // er
            if (grp == 0)      v = c1_relW[0 * 4096 + idx];
            else if (grp == 1) v = c1_relW[3 * 4096 + idx];
            else               v = c1_rootW[1 * 4096 + idx] + c1_rootW[2 * 4096 + idx];
        } else if (seg == 1) {   // sh
            if (grp == 0)      v = c1_relW[6 * 4096 + idx];
            else if (grp == 1) v = c1_relW[5 * 4096 + idx];
            else               v = c1_relW[1 * 4096 + idx];
        } else {                 // so
            if (grp == 0)      v = c1_relW[4 * 4096 + idx];
            else if (grp == 1) v = c1_relW[7 * 4096 + idx];
            else               v = c1_relW[2 * 4096 + idx];
        }
        g_G[i] = v;
    }
    for (int c = tid; c < 96; c += nth) {
        int grp = c / 32, cc = c % 32;
        float v;
        if (grp == 0)      v = c1_relb[0 * 32 + cc] + c1_relb[4 * 32 + cc] + c1_relb[6 * 32 + cc];
        else if (grp == 1) v = c1_relb[3 * 32 + cc] + c1_relb[5 * 32 + cc] + c1_relb[7 * 32 + cc];
        else               v = c1_relb[1 * 32 + cc] + c1_relb[2 * 32 + cc];
        g_Gb[c] = v;
    }
    for (int i = tid; i < 96 * 128; i += nth) {
        int k = i / 128, c = i % 128;
        float v;
        if (k < 32)      v = c2_relW[1 * 4096 + k * 128 + c];
        else if (k < 64) v = c2_relW[2 * 4096 + (k - 32) * 128 + c];
        else             v = c2_rootW[1 * 4096 + (k - 64) * 128 + c] +
                             c2_rootW[2 * 4096 + (k - 64) * 128 + c];
        g_G2[i] = v;
    }
    for (int c = tid; c < 128; c += nth)
        g_b2[c] = c2_relb[1 * 128 + c] + c2_relb[2 * 128 + c];
}

// ============================================================
// Kernel M: fused embeddings + convs + value MLP (2 CTAs/SM)
// ============================================================
// smem (floats): sX 1728 | sH1 2x1280=2560 (sVEC aliases) |
//                sE 80*132=10560 | sE2 7680 | sESS 3072  = 25600 (102400 B)
#define MAIN_SMEM_FLOATS 25600

__global__ void __launch_bounds__(NT, 2) main_kernel(
    const float* __restrict__ state,
    const float* __restrict__ wrW0, const float* __restrict__ wrb0,
    const float* __restrict__ wrW1, const float* __restrict__ wrb1,
    const float* __restrict__ whW0, const float* __restrict__ whb0,
    const float* __restrict__ whW1, const float* __restrict__ whb1,
    const float* __restrict__ woW0, const float* __restrict__ wob0,
    const float* __restrict__ woW1, const float* __restrict__ wob1,
    const float* __restrict__ vW0, const float* __restrict__ vb0,
    const float* __restrict__ vW1, const float* __restrict__ vb1,
    const float* __restrict__ vW2, const float* __restrict__ vb2,
    float* __restrict__ out) {
    extern __shared__ float sm[];
    float* sXh  = sm;                  // 8 x 20 x 7
    float* sXo  = sXh + BT * 140;      // 8 x 10 x 7
    float* sXr  = sXo + BT * 70;       // 8 x 6
    float* sH1  = sXr + BT * 6;        // 2 x (80 x 16) double-buffered k-slices
    float* sVEC = sH1;                 // alias: 8 x 96 (used after GEMM phase)
    float* sE   = sH1 + 2 * TILE * KQ; // 80 x 132
    float* sE2  = sE + TILE * SES;     // 8 x 30 x 32
    float* sESS = sE2 + BT * 960;      // 8 x 384  [er|sh|so]

    const int tid = threadIdx.x;
    const int b0 = blockIdx.x * BT;
    const int lane = tid & 31, warp = tid >> 5;

    // ---- stage inputs ----
    for (int i = tid; i < BT * 140; i += NT) {
        int b = i / 140, r = i % 140, nl = r / 7, f = r % 7;
        sXh[i] = state[(b0 + b) * 390 + nl * 13 + 6 + f];
    }
    for (int i = tid; i < BT * 70; i += NT) {
        int b = i / 70, r = i % 70, nl = r / 7, f = r % 7;
        sXo[i] = state[(b0 + b) * 390 + (20 + nl) * 13 + 6 + f];
    }
    if (tid < BT * 6) {
        int b = tid / 6, f = tid % 6;
        sXr[tid] = state[(b0 + b) * 390 + f];
    }
    __syncthreads();

    // ---- human/other embeddings + conv1 per-node terms ----
#pragma unroll
    for (int type = 0; type < 2; ++type) {
        const int npb     = (type == 0) ? 20 : 10;
        const int nodeb   = (type == 1) ? 20 : 0;
        const int xstride = (type == 0) ? 140 : 70;
        const float* W0g  = (type == 0) ? whW0 : woW0;
        const float* b0g  = (type == 0) ? whb0 : wob0;
        const float* b1g  = (type == 0) ? whb1 : wob1;
        const float* W1g  = (type == 0) ? whW1 : woW1;
        const float* Mg   = (type == 0) ? g_Mh : g_Mo;
        const float* sXt  = (type == 0) ? sXh : sXo;
        const int nrows   = BT * npb;     // 160 or 80: exact multiples of TILE
        const int sumoff  = (type == 0) ? 128 : 256;

        for (int rt = 0; rt < nrows; rt += TILE) {
            float acc[RPW][4];
#pragma unroll
            for (int i = 0; i < RPW; ++i)
#pragma unroll
                for (int j = 0; j < 4; ++j) acc[i][j] = 0.f;

            const int colq = tid & 15;       // layer1 producer mapping
            const int rowg = tid >> 4;       // 0..15 -> 5 rows each

            // produce slice 0 into buffer 0
            {
                float w0r[7];
#pragma unroll
                for (int k = 0; k < 7; ++k) w0r[k] = W0g[k * 256 + colq];
                const float bias = b0g[colq];
#pragma unroll
                for (int rr = 0; rr < 5; ++rr) {
                    const int r = rowg * 5 + rr;
                    const int gr = rt + r;
                    const int b = gr / npb, nl = gr - b * npb;
                    const float* x = &sXt[b * xstride + nl * 7];
                    float a = bias;
#pragma unroll
                    for (int k = 0; k < 7; ++k) a += x[k] * w0r[k];
                    sH1[r * KQ + colq] = fmaxf(a, 0.f);
                }
            }
            __syncthreads();

            for (int s = 0; s < 16; ++s) {
                // produce slice s+1 into the other buffer
                if (s < 15) {
                    float* buf = sH1 + ((s + 1) & 1) * (TILE * KQ);
                    const int kq = (s + 1) * KQ;
                    float w0r[7];
#pragma unroll
                    for (int k = 0; k < 7; ++k) w0r[k] = W0g[k * 256 + kq + colq];
                    const float bias = b0g[kq + colq];
#pragma unroll
                    for (int rr = 0; rr < 5; ++rr) {
                        const int r = rowg * 5 + rr;
                        const int gr = rt + r;
                        const int b = gr / npb, nl = gr - b * npb;
                        const float* x = &sXt[b * xstride + nl * 7];
                        float a = bias;
#pragma unroll
                        for (int k = 0; k < 7; ++k) a += x[k] * w0r[k];
                        buf[r * KQ + colq] = fmaxf(a, 0.f);
                    }
                }
                // consume slice s
                {
                    const float* cur = sH1 + (s & 1) * (TILE * KQ);
                    const int r0 = warp * RPW, c0 = lane * 4;
                    const float* Wp = W1g + c0;
                    const int kq = s * KQ;
#pragma unroll
                    for (int k = 0; k < KQ; k += 4) {
                        float a[RPW][4];
#pragma unroll
                        for (int i = 0; i < RPW; ++i) {
                            float4 t = *reinterpret_cast<const float4*>(&cur[(r0 + i) * KQ + k]);
                            a[i][0] = t.x; a[i][1] = t.y; a[i][2] = t.z; a[i][3] = t.w;
                        }
#pragma unroll
                        for (int kk = 0; kk < 4; ++kk) {
                            float4 w = *reinterpret_cast<const float4*>(&Wp[(kq + k + kk) * 128]);
#pragma unroll
                            for (int i = 0; i < RPW; ++i) {
                                acc[i][0] += a[i][kk] * w.x;
                                acc[i][1] += a[i][kk] * w.y;
                                acc[i][2] += a[i][kk] * w.z;
                                acc[i][3] += a[i][kk] * w.w;
                            }
                        }
                    }
                }
                __syncthreads();
            }

            // bias + relu -> sE
            {
                const int r0 = warp * RPW, c0 = lane * 4;
                float4 bb = *reinterpret_cast<const float4*>(&b1g[c0]);
#pragma unroll
                for (int i = 0; i < RPW; ++i) {
                    float4 o;
                    o.x = fmaxf(acc[i][0] + bb.x, 0.f);
                    o.y = fmaxf(acc[i][1] + bb.y, 0.f);
                    o.z = fmaxf(acc[i][2] + bb.z, 0.f);
                    o.w = fmaxf(acc[i][3] + bb.w, 0.f);
                    *reinterpret_cast<float4*>(&sE[(r0 + i) * SES + c0]) = o;
                }
            }
            __syncthreads();

            // per-batch sums: 256 threads, 2 chunks x 40 rows (batch-aligned)
            {
                const int c = tid & 127, chunk = tid >> 7;   // 2 chunks
                const int rbase = chunk * 40;
                int r = 0;
                while (r < 40) {
                    float s = 0.f;
#pragma unroll
                    for (int rr = 0; rr < 10; ++rr)
                        s += sE[(rbase + r + rr) * SES + c];
                    if (npb == 10) {
                        const int b = (rt + rbase + r) / 10;
                        sESS[b * 384 + sumoff + c] = s;
                        r += 10;
                    } else {
                        float s2 = 0.f;
#pragma unroll
                        for (int rr = 10; rr < 20; ++rr)
                            s2 += sE[(rbase + r + rr) * SES + c];
                        const int b = (rt + rbase + r) / 20;
                        sESS[b * 384 + sumoff + c] = s + s2;
                        r += 20;
                    }
                }
            }

            // e2 = e @ M (128 -> 32): 2-3 rows per thread, M reused
            {
                const int cq = tid & 7, rslot = tid >> 3;    // 32 row-slots
                const int nr = (rslot < 16) ? 3 : 2;         // 16*3 + 16*2 = 80
                float4 a0 = make_float4(0.f, 0.f, 0.f, 0.f), a1 = a0, a2 = a0;
                const float* E0 = &sE[rslot * SES];
                const float* E1 = &sE[(rslot + 32) * SES];
                const float* E2p = &sE[(rslot + 64) * SES];
                const float4* M4 = reinterpret_cast<const float4*>(Mg) + cq;
#pragma unroll 4
                for (int k = 0; k < 128; ++k) {
                    const float4 w = M4[k * 8];
                    const float e0 = E0[k], e1 = E1[k];
                    a0.x += e0 * w.x; a0.y += e0 * w.y; a0.z += e0 * w.z; a0.w += e0 * w.w;
                    a1.x += e1 * w.x; a1.y += e1 * w.y; a1.z += e1 * w.z; a1.w += e1 * w.w;
                    if (nr == 3) {
                        const float e2v = E2p[k];
                        a2.x += e2v * w.x; a2.y += e2v * w.y; a2.z += e2v * w.z; a2.w += e2v * w.w;
                    }
                }
#pragma unroll
                for (int j = 0; j < 3; ++j) {
                    if (j >= nr) break;
                    const int r = rslot + j * 32;
                    const int gr = rt + r;
                    const int b = gr / npb, node = nodeb + (gr - b * npb);
                    float4 v = (j == 0) ? a0 : (j == 1) ? a1 : a2;
                    *(reinterpret_cast<float4*>(&sE2[b * 960 + node * 32]) + cq) = v;
                }
            }
            __syncthreads();
        }
    }

    // ---- root embedding: 8 rows, direct path (h1 staged in sE) ----
    {
        const int col = tid;                 // 0..255
        float w0r[6];
#pragma unroll
        for (int k = 0; k < 6; ++k) w0r[k] = wrW0[k * 256 + col];
        const float bias = wrb0[col];
#pragma unroll
        for (int b = 0; b < BT; ++b) {
            const float* x = &sXr[b * 6];
            float a = bias;
#pragma unroll
            for (int k = 0; k < 6; ++k) a += x[k] * w0r[k];
            sE[b * 256 + col] = fmaxf(a, 0.f);
        }
    }
    __syncthreads();
    {
        // er = relu(h1 @ wrW1 + b1): 8x128 -> sESS[b*384 + 0..127]
        const int col = tid & 127, g = tid >> 7;     // g 0..1 -> 4 rows each
        float a[4];
        const float bias = wrb1[col];
#pragma unroll
        for (int i = 0; i < 4; ++i) a[i] = bias;
#pragma unroll 4
        for (int k = 0; k < 256; ++k) {
            const float w = wrW1[k * 128 + col];
#pragma unroll
            for (int i = 0; i < 4; ++i) a[i] += sE[(g * 4 + i) * 256 + k] * w;
        }
#pragma unroll
        for (int i = 0; i < 4; ++i)
            sESS[(g * 4 + i) * 384 + col] = fmaxf(a[i], 0.f);
    }
    __syncthreads();

    // conv1 commons + per-node relu sums -> sVEC (1 batch/thread-group)
    {
        const int b = tid >> 5, c0 = tid & 31;
        float a0 = g_Gb[c0], a1 = g_Gb[c0 + 32], a2 = g_Gb[c0 + 64];
        const float* in = &sESS[b * 384];
#pragma unroll 4
        for (int k = 0; k < 384; ++k) {
            const float av = in[k];
            a0 += av * g_G[k * 96 + c0];
            a1 += av * g_G[k * 96 + c0 + 32];
            a2 += av * g_G[k * 96 + c0 + 64];
        }
        float sh2 = 0.f, so2 = 0.f;
        const float* e2b = &sE2[b * 960];
#pragma unroll
        for (int n = 0; n < 20; ++n) sh2 += fmaxf(a0 + e2b[n * 32 + c0], 0.f);
#pragma unroll
        for (int n = 0; n < 10; ++n) so2 += fmaxf(a1 + e2b[(20 + n) * 32 + c0], 0.f);
        sVEC[b * 96 + c0]      = sh2;
        sVEC[b * 96 + 32 + c0] = so2;
        sVEC[b * 96 + 64 + c0] = fmaxf(a2, 0.f);
    }
    __syncthreads();

    // hr = relu([sh2|so2|r1] @ G2 + b2) -> sE as HR (8x128)
    {
        const int b = tid >> 5, cg = tid & 31;
        float a[4];
#pragma unroll
        for (int j = 0; j < 4; ++j) a[j] = g_b2[cg + 32 * j];
        const float* in = &sVEC[b * 96];
#pragma unroll 4
        for (int k = 0; k < 96; ++k) {
            const float av = in[k];
#pragma unroll
            for (int j = 0; j < 4; ++j) a[j] += av * g_G2[k * 128 + cg + 32 * j];
        }
#pragma unroll
        for (int j = 0; j < 4; ++j)
            sE[b * 128 + cg + 32 * j] = fmaxf(a[j], 0.f);
    }
    __syncthreads();

    // ---- value MLP ----
    // P = relu(HR @ vW0 + b0): 8x256 -> sE2[0..2047]
    {
        const int col = tid;                 // 0..255, 8 batches each
        float a[8];
        const float bias = vb0[col];
#pragma unroll
        for (int i = 0; i < 8; ++i) a[i] = bias;
#pragma unroll 4
        for (int k = 0; k < 128; ++k) {
            const float w = vW0[k * 256 + col];
#pragma unroll
            for (int i = 0; i < 8; ++i)
                a[i] += sE[i * 128 + k] * w;
        }
#pragma unroll
        for (int i = 0; i < 8; ++i)
            sE2[i * 256 + col] = fmaxf(a[i], 0.f);
    }
    __syncthreads();

    // Q = relu(P @ vW1 + b1): 8x128 -> sE2[2048..3071]
    {
        const int col = tid & 127, g = tid >> 7;     // g 0..1 -> 4 batches each
        float a[4];
        const float bias = vb1[col];
#pragma unroll
        for (int i = 0; i < 4; ++i) a[i] = bias;
#pragma unroll 4
        for (int k = 0; k < 256; ++k) {
            const float w = vW1[k * 128 + col];
#pragma unroll
            for (int i = 0; i < 4; ++i) a[i] += sE2[(g * 4 + i) * 256 + k] * w;
        }
#pragma unroll
        for (int i = 0; i < 4; ++i)
            sE2[2048 + (g * 4 + i) * 128 + col] = fmaxf(a[i], 0.f);
    }
    __syncthreads();

    // v = Q @ vW2 + b2: one warp per batch (8 warps = 8 batches)
    {
        const int b = warp, l = lane;
        float s = 0.f;
#pragma unroll
        for (int k = l; k < 128; k += 32) s += sE2[2048 + b * 128 + k] * vW2[k];
#pragma unroll
        for (int off = 16; off > 0; off >>= 1)
            s += __shfl_down_sync(0xffffffffu, s, off);
        if (l == 0) out[b0 + b] = s + vb2[0];
    }
}

// ============================================================
extern "C" void kernel_launch(void* const* d_in, const int* in_sizes, int n_in,
                              void* d_out, int out_size) {
    const float* state   = (const float*)d_in[0];
    const float* wrW0    = (const float*)d_in[2];
    const float* wrb0    = (const float*)d_in[3];
    const float* wrW1    = (const float*)d_in[4];
    const float* wrb1    = (const float*)d_in[5];
    const float* whW0    = (const float*)d_in[6];
    const float* whb0    = (const float*)d_in[7];
    const float* whW1    = (const float*)d_in[8];
    const float* whb1    = (const float*)d_in[9];
    const float* woW0    = (const float*)d_in[10];
    const float* wob0    = (const float*)d_in[11];
    const float* woW1    = (const float*)d_in[12];
    const float* wob1    = (const float*)d_in[13];
    const float* c1_relW = (const float*)d_in[14];
    const float* c1_relb = (const float*)d_in[15];
    const float* c1_rootW= (const float*)d_in[16];
    const float* c2_relW = (const float*)d_in[17];
    const float* c2_relb = (const float*)d_in[18];
    const float* c2_rootW= (const float*)d_in[19];
    const float* vW0     = (const float*)d_in[20];
    const float* vb0     = (const float*)d_in[21];
    const float* vW1     = (const float*)d_in[22];
    const float* vb1     = (const float*)d_in[23];
    const float* vW2     = (const float*)d_in[24];
    const float* vb2     = (const float*)d_in[25];
    float* out = (float*)d_out;

    cudaFuncSetAttribute(main_kernel, cudaFuncAttributeMaxDynamicSharedMemorySize,
                         MAIN_SMEM_FLOATS * 4);

    prep_kernel<<<64, 256>>>(c1_relW, c1_relb, c1_rootW, c2_relW, c2_relb, c2_rootW);

    main_kernel<<<BATCH / BT, NT, MAIN_SMEM_FLOATS * 4>>>(
        state, wrW0, wrb0, wrW1, wrb1, whW0, whb0, whW1, whb1,
        woW0, wob0, woW1, wob1,
        vW0, vb0, vW1, vb1, vW2, vb2, out);
}

// round 10
// speedup vs baseline: 2.7359x; 1.1462x over previous
#include <cuda_runtime.h>
#include <cuda_bf16.h>
#include <cstdint>

#define BATCH 8192
#define BT 8            // batches per block
#define NT 256          // threads per block
#define BUFS 18         // h1 slice row stride
#define SES 66          // sE row stride (half-width tile + pad)

// ---- device scratch ----
__device__ __align__(16) float g_Mh[128 * 32];
__device__ __align__(16) float g_Mo[128 * 32];
__device__ __align__(16) float g_G[384 * 96];
__device__ __align__(16) float g_Gb[96];
__device__ __align__(16) float g_G2[96 * 128];
__device__ __align__(16) float g_b2[128];
// B fragments, frag-ordered: [type(3)][ks(16)][ntAbs(16)][lane(32)] = {bhi0,bhi1,blo0,blo1}
__device__ __align__(16) uint4 g_Bfrag[3 * 16 * 16 * 32];

__device__ __forceinline__ uint32_t bf2_bits(__nv_bfloat162 h) {
    return *reinterpret_cast<uint32_t*>(&h);
}
__device__ __forceinline__ uint32_t pack_hi(float a, float b) {   // a -> low half
    return bf2_bits(__floats2bfloat162_rn(a, b));
}
__device__ __forceinline__ void split_pair(float x, float y, uint32_t& hi, uint32_t& lo) {
    __nv_bfloat16 hx = __float2bfloat16_rn(x), hy = __float2bfloat16_rn(y);
    __nv_bfloat16 lx = __float2bfloat16_rn(x - __bfloat162float(hx));
    __nv_bfloat16 ly = __float2bfloat16_rn(y - __bfloat162float(hy));
    __nv_bfloat162 h = __halves2bfloat162(hx, hy);
    __nv_bfloat162 l = __halves2bfloat162(lx, ly);
    hi = bf2_bits(h); lo = bf2_bits(l);
}
__device__ __forceinline__ void mma_bf16(float& d0, float& d1, float& d2, float& d3,
                                         uint32_t a0, uint32_t a1, uint32_t a2, uint32_t a3,
                                         uint32_t b0, uint32_t b1) {
    asm volatile(
        "mma.sync.aligned.m16n8k16.row.col.f32.bf16.bf16.f32 "
        "{%0,%1,%2,%3}, {%4,%5,%6,%7}, {%8,%9}, {%0,%1,%2,%3};"
        : "+f"(d0), "+f"(d1), "+f"(d2), "+f"(d3)
        : "r"(a0), "r"(a1), "r"(a2), "r"(a3), "r"(b0), "r"(b1));
}

// ============================================================
// Kernel P: fold conv weights + build bf16 hi/lo B fragments
// ============================================================
__global__ void prep_kernel(const float* __restrict__ c1_relW,
                            const float* __restrict__ c1_relb,
                            const float* __restrict__ c1_rootW,
                            const float* __restrict__ c2_relW,
                            const float* __restrict__ c2_relb,
                            const float* __restrict__ c2_rootW,
                            const float* __restrict__ whW1,
                            const float* __restrict__ woW1,
                            const float* __restrict__ wrW1) {
    int tid = blockIdx.x * blockDim.x + threadIdx.x;
    int nth = gridDim.x * blockDim.x;

    for (int i = tid; i < 128 * 32; i += nth) {
        g_Mh[i] = c1_rootW[0 * 4096 + i] + c1_rootW[4 * 4096 + i] +
                  c1_rootW[6 * 4096 + i] - c1_relW[6 * 4096 + i];
        g_Mo[i] = c1_rootW[3 * 4096 + i] + c1_rootW[5 * 4096 + i] +
                  c1_rootW[7 * 4096 + i] - c1_relW[7 * 4096 + i];
    }
    for (int i = tid; i < 384 * 96; i += nth) {
        int k = i / 96, c = i % 96;
        int grp = c / 32, cc = c % 32;
        int seg = k / 128, kk = k % 128;
        int idx = kk * 32 + cc;
        float v;
        if (seg == 0) {
            if (grp == 0)      v = c1_relW[0 * 4096 + idx];
            else if (grp == 1) v = c1_relW[3 * 4096 + idx];
            else               v = c1_rootW[1 * 4096 + idx] + c1_rootW[2 * 4096 + idx];
        } else if (seg == 1) {
            if (grp == 0)      v = c1_relW[6 * 4096 + idx];
            else if (grp == 1) v = c1_relW[5 * 4096 + idx];
            else               v = c1_relW[1 * 4096 + idx];
        } else {
            if (grp == 0)      v = c1_relW[4 * 4096 + idx];
            else if (grp == 1) v = c1_relW[7 * 4096 + idx];
            else               v = c1_relW[2 * 4096 + idx];
        }
        g_G[i] = v;
    }
    for (int c = tid; c < 96; c += nth) {
        int grp = c / 32, cc = c % 32;
        float v;
        if (grp == 0)      v = c1_relb[0 * 32 + cc] + c1_relb[4 * 32 + cc] + c1_relb[6 * 32 + cc];
        else if (grp == 1) v = c1_relb[3 * 32 + cc] + c1_relb[5 * 32 + cc] + c1_relb[7 * 32 + cc];
        else               v = c1_relb[1 * 32 + cc] + c1_relb[2 * 32 + cc];
        g_Gb[c] = v;
    }
    for (int i = tid; i < 96 * 128; i += nth) {
        int k = i / 128, c = i % 128;
        float v;
        if (k < 32)      v = c2_relW[1 * 4096 + k * 128 + c];
        else if (k < 64) v = c2_relW[2 * 4096 + (k - 32) * 128 + c];
        else             v = c2_rootW[1 * 4096 + (k - 64) * 128 + c] +
                             c2_rootW[2 * 4096 + (k - 64) * 128 + c];
        g_G2[i] = v;
    }
    for (int c = tid; c < 128; c += nth)
        g_b2[c] = c2_relb[1 * 128 + c] + c2_relb[2 * 128 + c];

    // B fragments (col-major frag for mma.m16n8k16): per (type,ks,ntAbs,lane)
    for (int i = tid; i < 3 * 16 * 16 * 32; i += nth) {
        int lane = i & 31, ntA = (i >> 5) & 15, ks = (i >> 9) & 15, ty = i >> 13;
        const float* W = (ty == 0) ? whW1 : (ty == 1) ? woW1 : wrW1;
        int n = ntA * 8 + (lane >> 2);
        int k0 = ks * 16 + 2 * (lane & 3);
        uint32_t h0, l0, h1, l1;
        split_pair(W[k0 * 128 + n], W[(k0 + 1) * 128 + n], h0, l0);
        split_pair(W[(k0 + 8) * 128 + n], W[(k0 + 9) * 128 + n], h1, l1);
        g_Bfrag[i] = make_uint4(h0, h1, l0, l1);
    }
}

// ============================================================
// Kernel M: tensor-core GEMM + fused epilogue
// ============================================================
// smem (floats): sX 1728 | sBuf 2*128*18=4608 | sE 128*66=8448 | sE2 7680 | sESS 3072
#define MAIN_SMEM_FLOATS 25536   // 102144 bytes -> 2 CTAs/SM

__global__ void __launch_bounds__(NT, 2) main_kernel(
    const float* __restrict__ state,
    const float* __restrict__ wrW0, const float* __restrict__ wrb0,
    const float* __restrict__ wrb1,
    const float* __restrict__ whW0, const float* __restrict__ whb0,
    const float* __restrict__ whb1,
    const float* __restrict__ woW0, const float* __restrict__ wob0,
    const float* __restrict__ wob1,
    const float* __restrict__ vW0, const float* __restrict__ vb0,
    const float* __restrict__ vW1, const float* __restrict__ vb1,
    const float* __restrict__ vW2, const float* __restrict__ vb2,
    float* __restrict__ out) {
    extern __shared__ float sm[];
    float* sXh  = sm;                    // 8 x 20 x 7
    float* sXo  = sXh + BT * 140;        // 8 x 10 x 7
    float* sXr  = sXo + BT * 70;         // 8 x 6
    float* sBuf = sXr + BT * 6;          // 2 x 128 x 18 h1 k-slices
    float* sE   = sBuf + 2 * 128 * BUFS; // 128 x 66 (half-N e tile; later HR + sVEC)
    float* sE2  = sE + 128 * SES;        // 8 x 30 x 32 (later value scratch)
    float* sESS = sE2 + BT * 960;        // 8 x 384 [er|sh|so]
    float* sVEC = sE + 1024;             // alias (after GEMM phase)

    const int tid = threadIdx.x;
    const int b0 = blockIdx.x * BT;
    const int lane = tid & 31, warp = tid >> 5;

    for (int i = tid; i < BT * 140; i += NT) {
        int b = i / 140, r = i % 140, nl = r / 7, f = r % 7;
        sXh[i] = state[(b0 + b) * 390 + nl * 13 + 6 + f];
    }
    for (int i = tid; i < BT * 70; i += NT) {
        int b = i / 70, r = i % 70, nl = r / 7, f = r % 7;
        sXo[i] = state[(b0 + b) * 390 + (20 + nl) * 13 + 6 + f];
    }
    if (tid < BT * 6) {
        int b = tid / 6, f = tid % 6;
        sXr[tid] = state[(b0 + b) * 390 + f];
    }
    for (int i = tid; i < BT * 384; i += NT) sESS[i] = 0.f;
    __syncthreads();

    // producer thread mapping (fixed across passes)
    const int c2 = tid & 7;              // cols {c2, c2+8} of each k-slice
    const int rowgrp = tid >> 3;         // 4 local rows: rowgrp*4..+3

    // consumer (mma) mapping
    const int t4 = lane & 3;
    const int rql = lane >> 2;           // 0..7

    for (int pass = 0; pass < 4; ++pass) {
        const int g = pass >> 1, nh = pass & 1;

        // --- warp strip config ---
        int tI;
        if (g == 0) tI = 0;
        else tI = (warp < 2) ? 0 : (warp < 7) ? 1 : 2;
        const float* b1g = (tI == 0) ? whb1 : (tI == 1) ? wob1 : wrb1;

        // --- producer config: type + x regs (4 rows x 7) ---
        int ptype;
        {
            int absr = g * 128 + rowgrp * 4;
            ptype = (absr < 160) ? 0 : (absr < 240) ? 1 : 2;
        }
        const float* W0g = (ptype == 0) ? whW0 : (ptype == 1) ? woW0 : wrW0;
        const float* b0g = (ptype == 0) ? whb0 : (ptype == 1) ? wob0 : wrb0;
        float xr[4][7];
#pragma unroll
        for (int i = 0; i < 4; ++i) {
            int absr = g * 128 + rowgrp * 4 + i;
            const float* src;
            int nf;
            if (absr < 160)      { int b = absr / 20; src = sXh + b * 140 + (absr % 20) * 7; nf = 7; }
            else if (absr < 240) { int idx = absr - 160; int b = idx / 10; src = sXo + b * 70 + (idx % 10) * 7; nf = 7; }
            else                 { int b = absr - 240; src = (b < 8) ? (sXr + b * 6) : nullptr; nf = 6; }
#pragma unroll
            for (int f = 0; f < 7; ++f)
                xr[i][f] = (src && f < nf) ? src[f] : 0.f;
        }

        float acc[8][4];
#pragma unroll
        for (int n = 0; n < 8; ++n)
#pragma unroll
            for (int j = 0; j < 4; ++j) acc[n][j] = 0.f;

        // --- produce k-slice 0 ---
        {
            float* buf = sBuf;
#pragma unroll
            for (int cc = 0; cc < 2; ++cc) {
                const int c = c2 + cc * 8;
                float w[7];
#pragma unroll
                for (int f = 0; f < 6; ++f) w[f] = W0g[f * 256 + c];
                w[6] = (ptype == 2) ? 0.f : W0g[6 * 256 + c];
                const float bias = b0g[c];
#pragma unroll
                for (int i = 0; i < 4; ++i) {
                    float v = bias;
#pragma unroll
                    for (int f = 0; f < 7; ++f) v += xr[i][f] * w[f];
                    buf[(rowgrp * 4 + i) * BUFS + c] = fmaxf(v, 0.f);
                }
            }
        }
        __syncthreads();

        const int r0 = warp * 16 + rql;
        for (int ks = 0; ks < 16; ++ks) {
            if (ks < 15) {   // produce slice ks+1
                float* buf = sBuf + ((ks + 1) & 1) * (128 * BUFS);
                const int k0 = (ks + 1) * 16;
#pragma unroll
                for (int cc = 0; cc < 2; ++cc) {
                    const int c = c2 + cc * 8;
                    float w[7];
#pragma unroll
                    for (int f = 0; f < 6; ++f) w[f] = W0g[f * 256 + k0 + c];
                    w[6] = (ptype == 2) ? 0.f : W0g[6 * 256 + k0 + c];
                    const float bias = b0g[k0 + c];
#pragma unroll
                    for (int i = 0; i < 4; ++i) {
                        float v = bias;
#pragma unroll
                        for (int f = 0; f < 7; ++f) v += xr[i][f] * w[f];
                        buf[(rowgrp * 4 + i) * BUFS + c] = fmaxf(v, 0.f);
                    }
                }
            }
            // consume slice ks
            {
                const float* buf = sBuf + (ks & 1) * (128 * BUFS);
                float2 p00 = *reinterpret_cast<const float2*>(&buf[r0 * BUFS + 2 * t4]);
                float2 p01 = *reinterpret_cast<const float2*>(&buf[r0 * BUFS + 2 * t4 + 8]);
                float2 p10 = *reinterpret_cast<const float2*>(&buf[(r0 + 8) * BUFS + 2 * t4]);
                float2 p11 = *reinterpret_cast<const float2*>(&buf[(r0 + 8) * BUFS + 2 * t4 + 8]);
                uint32_t ah0, al0, ah1, al1, ah2, al2, ah3, al3;
                split_pair(p00.x, p00.y, ah0, al0);
                split_pair(p10.x, p10.y, ah1, al1);
                split_pair(p01.x, p01.y, ah2, al2);
                split_pair(p11.x, p11.y, ah3, al3);

                const uint4* Bp = g_Bfrag + (((tI * 16 + ks) * 16 + nh * 8) * 32) + lane;
#pragma unroll
                for (int nt = 0; nt < 8; ++nt) {
                    uint4 v = Bp[nt * 32];
                    mma_bf16(acc[nt][0], acc[nt][1], acc[nt][2], acc[nt][3],
                             ah0, ah1, ah2, ah3, v.x, v.y);
                    mma_bf16(acc[nt][0], acc[nt][1], acc[nt][2], acc[nt][3],
                             al0, al1, al2, al3, v.x, v.y);
                    mma_bf16(acc[nt][0], acc[nt][1], acc[nt][2], acc[nt][3],
                             ah0, ah1, ah2, ah3, v.z, v.w);
                }
            }
            __syncthreads();
        }

        // bias + relu -> sE (half-N tile, local cols 0..63)
        {
#pragma unroll
            for (int nt = 0; nt < 8; ++nt) {
                const int c = nt * 8 + 2 * t4;
                const float be = b1g[nh * 64 + c], bo = b1g[nh * 64 + c + 1];
                float2 e0, e1;
                e0.x = fmaxf(acc[nt][0] + be, 0.f);
                e0.y = fmaxf(acc[nt][1] + bo, 0.f);
                e1.x = fmaxf(acc[nt][2] + be, 0.f);
                e1.y = fmaxf(acc[nt][3] + bo, 0.f);
                *reinterpret_cast<float2*>(&sE[r0 * SES + c]) = e0;
                *reinterpret_cast<float2*>(&sE[(r0 + 8) * SES + c]) = e1;
            }
        }
        __syncthreads();

        // per-batch sums -> sESS (+=), segment tables per group
        {
            const int c = tid & 63, slot = tid >> 6;
            const int nsegs = (g == 0) ? 7 : 10;
            for (int i = slot; i < nsegs; i += 4) {
                int s, e, b, off;
                if (g == 0) { s = 20 * i; e = min(128, s + 20); b = i; off = 128; }
                else if (i == 0) { s = 0; e = 12; b = 6; off = 128; }
                else if (i == 1) { s = 12; e = 32; b = 7; off = 128; }
                else { int j = i - 2; s = 32 + 10 * j; e = s + 10; b = j; off = 256; }
                float sum = 0.f;
                for (int r = s; r < e; ++r) sum += sE[r * SES + c];
                sESS[b * 384 + off + nh * 64 + c] += sum;
            }
        }
        // er copy (group 1 only)
        if (g == 1) {
            for (int i = tid; i < 512; i += NT) {
                int b = i >> 6, c = i & 63;
                sESS[b * 384 + nh * 64 + c] = sE[(112 + b) * SES + c];
            }
        }
        // e2 = e @ M (accumulate over halves)
        {
            const int cq = tid & 7, rs = tid >> 3;
            const int nrowmax = (g == 0) ? 128 : 112;
#pragma unroll
            for (int j = 0; j < 4; ++j) {
                const int r = rs + j * 32;
                if (r >= nrowmax) break;
                const int absr = g * 128 + r;
                int b, node;
                const float* Mg;
                if (absr < 160) { b = absr / 20; node = absr % 20; Mg = g_Mh; }
                else { int idx = absr - 160; b = idx / 10; node = 20 + idx % 10; Mg = g_Mo; }
                const float4* M4 = reinterpret_cast<const float4*>(Mg) + cq;
                const float* Er = &sE[r * SES];
                float4 a4 = make_float4(0.f, 0.f, 0.f, 0.f);
#pragma unroll 4
                for (int k = 0; k < 64; ++k) {
                    const float ev = Er[k];
                    const float4 w4 = M4[(nh * 64 + k) * 8];
                    a4.x += ev * w4.x; a4.y += ev * w4.y;
                    a4.z += ev * w4.z; a4.w += ev * w4.w;
                }
                float4* dst = reinterpret_cast<float4*>(&sE2[b * 960 + node * 32]) + cq;
                if (nh == 0) *dst = a4;
                else {
                    float4 p = *dst;
                    p.x += a4.x; p.y += a4.y; p.z += a4.z; p.w += a4.w;
                    *dst = p;
                }
            }
        }
        __syncthreads();
    }

    // ---- conv1 commons + per-node relu sums -> sVEC ----
    {
        const int b = tid >> 5, c0 = tid & 31;
        float a0 = g_Gb[c0], a1 = g_Gb[c0 + 32], a2 = g_Gb[c0 + 64];
        const float* in = &sESS[b * 384];
#pragma unroll 4
        for (int k = 0; k < 384; ++k) {
            const float av = in[k];
            a0 += av * g_G[k * 96 + c0];
            a1 += av * g_G[k * 96 + c0 + 32];
            a2 += av * g_G[k * 96 + c0 + 64];
        }
        float sh2 = 0.f, so2 = 0.f;
        const float* e2b = &sE2[b * 960];
#pragma unroll
        for (int n = 0; n < 20; ++n) sh2 += fmaxf(a0 + e2b[n * 32 + c0], 0.f);
#pragma unroll
        for (int n = 0; n < 10; ++n) so2 += fmaxf(a1 + e2b[(20 + n) * 32 + c0], 0.f);
        sVEC[b * 96 + c0]      = sh2;
        sVEC[b * 96 + 32 + c0] = so2;
        sVEC[b * 96 + 64 + c0] = fmaxf(a2, 0.f);
    }
    __syncthreads();

    // ---- hr = relu([sh2|so2|r1] @ G2 + b2) -> sE[0..1023] ----
    {
        const int b = tid >> 5, cg = tid & 31;
        float a[4];
#pragma unroll
        for (int j = 0; j < 4; ++j) a[j] = g_b2[cg + 32 * j];
        const float* in = &sVEC[b * 96];
#pragma unroll 4
        for (int k = 0; k < 96; ++k) {
            const float av = in[k];
#pragma unroll
            for (int j = 0; j < 4; ++j) a[j] += av * g_G2[k * 128 + cg + 32 * j];
        }
#pragma unroll
        for (int j = 0; j < 4; ++j)
            sE[b * 128 + cg + 32 * j] = fmaxf(a[j], 0.f);
    }
    __syncthreads();

    // ---- value MLP ----
    {
        const int col = tid;
        float a[8];
        const float bias = vb0[col];
#pragma unroll
        for (int i = 0; i < 8; ++i) a[i] = bias;
#pragma unroll 4
        for (int k = 0; k < 128; ++k) {
            const float w = vW0[k * 256 + col];
#pragma unroll
            for (int i = 0; i < 8; ++i) a[i] += sE[i * 128 + k] * w;
        }
#pragma unroll
        for (int i = 0; i < 8; ++i)
            sE2[i * 256 + col] = fmaxf(a[i], 0.f);
    }
    __syncthreads();
    {
        const int col = tid & 127, gq = tid >> 7;
        float a[4];
        const float bias = vb1[col];
#pragma unroll
        for (int i = 0; i < 4; ++i) a[i] = bias;
#pragma unroll 4
        for (int k = 0; k < 256; ++k) {
            const float w = vW1[k * 128 + col];
#pragma unroll
            for (int i = 0; i < 4; ++i) a[i] += sE2[(gq * 4 + i) * 256 + k] * w;
        }
#pragma unroll
        for (int i = 0; i < 4; ++i)
            sE2[2048 + (gq * 4 + i) * 128 + col] = fmaxf(a[i], 0.f);
    }
    __syncthreads();
    {
        const int b = warp, l = lane;
        float s = 0.f;
#pragma unroll
        for (int k = l; k < 128; k += 32) s += sE2[2048 + b * 128 + k] * vW2[k];
#pragma unroll
        for (int off = 16; off > 0; off >>= 1)
            s += __shfl_down_sync(0xffffffffu, s, off);
        if (l == 0) out[b0 + b] = s + vb2[0];
    }
}

// ============================================================
extern "C" void kernel_launch(void* const* d_in, const int* in_sizes, int n_in,
                              void* d_out, int out_size) {
    const float* state   = (const float*)d_in[0];
    const float* wrW0    = (const float*)d_in[2];
    const float* wrb0    = (const float*)d_in[3];
    const float* wrW1    = (const float*)d_in[4];
    const float* wrb1    = (const float*)d_in[5];
    const float* whW0    = (const float*)d_in[6];
    const float* whb0    = (const float*)d_in[7];
    const float* whW1    = (const float*)d_in[8];
    const float* whb1    = (const float*)d_in[9];
    const float* woW0    = (const float*)d_in[10];
    const float* wob0    = (const float*)d_in[11];
    const float* woW1    = (const float*)d_in[12];
    const float* wob1    = (const float*)d_in[13];
    const float* c1_relW = (const float*)d_in[14];
    const float* c1_relb = (const float*)d_in[15];
    const float* c1_rootW= (const float*)d_in[16];
    const float* c2_relW = (const float*)d_in[17];
    const float* c2_relb = (const float*)d_in[18];
    const float* c2_rootW= (const float*)d_in[19];
    const float* vW0     = (const float*)d_in[20];
    const float* vb0     = (const float*)d_in[21];
    const float* vW1     = (const float*)d_in[22];
    const float* vb1     = (const float*)d_in[23];
    const float* vW2     = (const float*)d_in[24];
    const float* vb2     = (const float*)d_in[25];
    float* out = (float*)d_out;

    cudaFuncSetAttribute(main_kernel, cudaFuncAttributeMaxDynamicSharedMemorySize,
                         MAIN_SMEM_FLOATS * 4);

    prep_kernel<<<96, 256>>>(c1_relW, c1_relb, c1_rootW, c2_relW, c2_relb, c2_rootW,
                             whW1, woW1, wrW1);

    main_kernel<<<BATCH / BT, NT, MAIN_SMEM_FLOATS * 4>>>(
        state, wrW0, wrb0, wrb1, whW0, whb0, whb1,
        woW0, wob0, wob1,
        vW0, vb0, vW1, vb1, vW2, vb2, out);
}

// round 11
// speedup vs baseline: 2.7382x; 1.0008x over previous
#include <cuda_runtime.h>
#include <cuda_bf16.h>
#include <cstdint>

#define BATCH 8192
#define BT 8            // batches per block
#define NT 256          // threads per block
#define BUFS 18         // h1 slice row stride
#define SES 66          // sE row stride (half-width tile + pad)

// ---- device scratch ----
__device__ __align__(16) float g_Mh[128 * 32];
__device__ __align__(16) float g_Mo[128 * 32];
__device__ __align__(16) float g_G[384 * 96];
__device__ __align__(16) float g_Gb[96];
__device__ __align__(16) float g_G2[96 * 128];
__device__ __align__(16) float g_b2[128];
// B fragments, frag-ordered: [type(3)][ks(16)][ntAbs(16)][lane(32)] = {bhi0,bhi1,blo0,blo1}
__device__ __align__(16) uint4 g_Bfrag[3 * 16 * 16 * 32];

__device__ __forceinline__ uint32_t bf2_bits(__nv_bfloat162 h) {
    return *reinterpret_cast<uint32_t*>(&h);
}
__device__ __forceinline__ uint32_t pack_hi(float a, float b) {   // a -> low half
    return bf2_bits(__floats2bfloat162_rn(a, b));
}
__device__ __forceinline__ void split_pair(float x, float y, uint32_t& hi, uint32_t& lo) {
    __nv_bfloat16 hx = __float2bfloat16_rn(x), hy = __float2bfloat16_rn(y);
    __nv_bfloat16 lx = __float2bfloat16_rn(x - __bfloat162float(hx));
    __nv_bfloat16 ly = __float2bfloat16_rn(y - __bfloat162float(hy));
    __nv_bfloat162 h = __halves2bfloat162(hx, hy);
    __nv_bfloat162 l = __halves2bfloat162(lx, ly);
    hi = bf2_bits(h); lo = bf2_bits(l);
}
__device__ __forceinline__ void mma_bf16(float& d0, float& d1, float& d2, float& d3,
                                         uint32_t a0, uint32_t a1, uint32_t a2, uint32_t a3,
                                         uint32_t b0, uint32_t b1) {
    asm volatile(
        "mma.sync.aligned.m16n8k16.row.col.f32.bf16.bf16.f32 "
        "{%0,%1,%2,%3}, {%4,%5,%6,%7}, {%8,%9}, {%0,%1,%2,%3};"
        : "+f"(d0), "+f"(d1), "+f"(d2), "+f"(d3)
        : "r"(a0), "r"(a1), "r"(a2), "r"(a3), "r"(b0), "r"(b1));
}

// ============================================================
// Kernel P: fold conv weights + build bf16 hi/lo B fragments
// ============================================================
__global__ void prep_kernel(const float* __restrict__ c1_relW,
                            const float* __restrict__ c1_relb,
                            const float* __restrict__ c1_rootW,
                            const float* __restrict__ c2_relW,
                            const float* __restrict__ c2_relb,
                            const float* __restrict__ c2_rootW,
                            const float* __restrict__ whW1,
                            const float* __restrict__ woW1,
                            const float* __restrict__ wrW1) {
    int tid = blockIdx.x * blockDim.x + threadIdx.x;
    int nth = gridDim.x * blockDim.x;

    for (int i = tid; i < 128 * 32; i += nth) {
        g_Mh[i] = c1_rootW[0 * 4096 + i] + c1_rootW[4 * 4096 + i] +
                  c1_rootW[6 * 4096 + i] - c1_relW[6 * 4096 + i];
        g_Mo[i] = c1_rootW[3 * 4096 + i] + c1_rootW[5 * 4096 + i] +
                  c1_rootW[7 * 4096 + i] - c1_relW[7 * 4096 + i];
    }
    for (int i = tid; i < 384 * 96; i += nth) {
        int k = i / 96, c = i % 96;
        int grp = c / 32, cc = c % 32;
        int seg = k / 128, kk = k % 128;
        int idx = kk * 32 + cc;
        float v;
        if (seg == 0) {
            if (grp == 0)      v = c1_relW[0 * 4096 + idx];
            else if (grp == 1) v = c1_relW[3 * 4096 + idx];
            else               v = c1_rootW[1 * 4096 + idx] + c1_rootW[2 * 4096 + idx];
        } else if (seg == 1) {
            if (grp == 0)      v = c1_relW[6 * 4096 + idx];
            else if (grp == 1) v = c1_relW[5 * 4096 + idx];
            else               v = c1_relW[1 * 4096 + idx];
        } else {
            if (grp == 0)      v = c1_relW[4 * 4096 + idx];
            else if (grp == 1) v = c1_relW[7 * 4096 + idx];
            else               v = c1_relW[2 * 4096 + idx];
        }
        g_G[i] = v;
    }
    for (int c = tid; c < 96; c += nth) {
        int grp = c / 32, cc = c % 32;
        float v;
        if (grp == 0)      v = c1_relb[0 * 32 + cc] + c1_relb[4 * 32 + cc] + c1_relb[6 * 32 + cc];
        else if (grp == 1) v = c1_relb[3 * 32 + cc] + c1_relb[5 * 32 + cc] + c1_relb[7 * 32 + cc];
        else               v = c1_relb[1 * 32 + cc] + c1_relb[2 * 32 + cc];
        g_Gb[c] = v;
    }
    for (int i = tid; i < 96 * 128; i += nth) {
        int k = i / 128, c = i % 128;
        float v;
        if (k < 32)      v = c2_relW[1 * 4096 + k * 128 + c];
        else if (k < 64) v = c2_relW[2 * 4096 + (k - 32) * 128 + c];
        else             v = c2_rootW[1 * 4096 + (k - 64) * 128 + c] +
                             c2_rootW[2 * 4096 + (k - 64) * 128 + c];
        g_G2[i] = v;
    }
    for (int c = tid; c < 128; c += nth)
        g_b2[c] = c2_relb[1 * 128 + c] + c2_relb[2 * 128 + c];

    // B fragments (col-major frag for mma.m16n8k16): per (type,ks,ntAbs,lane)
    for (int i = tid; i < 3 * 16 * 16 * 32; i += nth) {
        int lane = i & 31, ntA = (i >> 5) & 15, ks = (i >> 9) & 15, ty = i >> 13;
        const float* W = (ty == 0) ? whW1 : (ty == 1) ? woW1 : wrW1;
        int n = ntA * 8 + (lane >> 2);
        int k0 = ks * 16 + 2 * (lane & 3);
        uint32_t h0, l0, h1, l1;
        split_pair(W[k0 * 128 + n], W[(k0 + 1) * 128 + n], h0, l0);
        split_pair(W[(k0 + 8) * 128 + n], W[(k0 + 9) * 128 + n], h1, l1);
        g_Bfrag[i] = make_uint4(h0, h1, l0, l1);
    }
}

// ============================================================
// Kernel M: tensor-core GEMM + fused epilogue
// ============================================================
// smem (floats): sX 1728 | sBuf 2*128*18=4608 | sE 128*66=8448 | sE2 7680 | sESS 3072
#define MAIN_SMEM_FLOATS 25536   // 102144 bytes -> 2 CTAs/SM

__global__ void __launch_bounds__(NT, 2) main_kernel(
    const float* __restrict__ state,
    const float* __restrict__ wrW0, const float* __restrict__ wrb0,
    const float* __restrict__ wrb1,
    const float* __restrict__ whW0, const float* __restrict__ whb0,
    const float* __restrict__ whb1,
    const float* __restrict__ woW0, const float* __restrict__ wob0,
    const float* __restrict__ wob1,
    const float* __restrict__ vW0, const float* __restrict__ vb0,
    const float* __restrict__ vW1, const float* __restrict__ vb1,
    const float* __restrict__ vW2, const float* __restrict__ vb2,
    float* __restrict__ out) {
    extern __shared__ float sm[];
    float* sXh  = sm;                    // 8 x 20 x 7
    float* sXo  = sXh + BT * 140;        // 8 x 10 x 7
    float* sXr  = sXo + BT * 70;         // 8 x 6
    float* sBuf = sXr + BT * 6;          // 2 x 128 x 18 h1 k-slices
    float* sE   = sBuf + 2 * 128 * BUFS; // 128 x 66 (half-N e tile; later HR + sVEC)
    float* sE2  = sE + 128 * SES;        // 8 x 30 x 32 (later value scratch)
    float* sESS = sE2 + BT * 960;        // 8 x 384 [er|sh|so]
    float* sVEC = sE + 1024;             // alias (after GEMM phase)

    const int tid = threadIdx.x;
    const int b0 = blockIdx.x * BT;
    const int lane = tid & 31, warp = tid >> 5;

    for (int i = tid; i < BT * 140; i += NT) {
        int b = i / 140, r = i % 140, nl = r / 7, f = r % 7;
        sXh[i] = state[(b0 + b) * 390 + nl * 13 + 6 + f];
    }
    for (int i = tid; i < BT * 70; i += NT) {
        int b = i / 70, r = i % 70, nl = r / 7, f = r % 7;
        sXo[i] = state[(b0 + b) * 390 + (20 + nl) * 13 + 6 + f];
    }
    if (tid < BT * 6) {
        int b = tid / 6, f = tid % 6;
        sXr[tid] = state[(b0 + b) * 390 + f];
    }
    for (int i = tid; i < BT * 384; i += NT) sESS[i] = 0.f;
    __syncthreads();

    // producer thread mapping (fixed across passes)
    const int c2 = tid & 7;              // cols {c2, c2+8} of each k-slice
    const int rowgrp = tid >> 3;         // 4 local rows: rowgrp*4..+3

    // consumer (mma) mapping
    const int t4 = lane & 3;
    const int rql = lane >> 2;           // 0..7

    for (int pass = 0; pass < 4; ++pass) {
        const int g = pass >> 1, nh = pass & 1;

        // --- warp strip config ---
        int tI;
        if (g == 0) tI = 0;
        else tI = (warp < 2) ? 0 : (warp < 7) ? 1 : 2;
        const float* b1g = (tI == 0) ? whb1 : (tI == 1) ? wob1 : wrb1;

        // --- producer config: type + x regs (4 rows x 7) ---
        int ptype;
        {
            int absr = g * 128 + rowgrp * 4;
            ptype = (absr < 160) ? 0 : (absr < 240) ? 1 : 2;
        }
        const float* W0g = (ptype == 0) ? whW0 : (ptype == 1) ? woW0 : wrW0;
        const float* b0g = (ptype == 0) ? whb0 : (ptype == 1) ? wob0 : wrb0;
        float xr[4][7];
#pragma unroll
        for (int i = 0; i < 4; ++i) {
            int absr = g * 128 + rowgrp * 4 + i;
            const float* src;
            int nf;
            if (absr < 160)      { int b = absr / 20; src = sXh + b * 140 + (absr % 20) * 7; nf = 7; }
            else if (absr < 240) { int idx = absr - 160; int b = idx / 10; src = sXo + b * 70 + (idx % 10) * 7; nf = 7; }
            else                 { int b = absr - 240; src = (b < 8) ? (sXr + b * 6) : nullptr; nf = 6; }
#pragma unroll
            for (int f = 0; f < 7; ++f)
                xr[i][f] = (src && f < nf) ? src[f] : 0.f;
        }

        float acc[8][4];
#pragma unroll
        for (int n = 0; n < 8; ++n)
#pragma unroll
            for (int j = 0; j < 4; ++j) acc[n][j] = 0.f;

        // --- produce k-slice 0 ---
        {
            float* buf = sBuf;
#pragma unroll
            for (int cc = 0; cc < 2; ++cc) {
                const int c = c2 + cc * 8;
                float w[7];
#pragma unroll
                for (int f = 0; f < 6; ++f) w[f] = W0g[f * 256 + c];
                w[6] = (ptype == 2) ? 0.f : W0g[6 * 256 + c];
                const float bias = b0g[c];
#pragma unroll
                for (int i = 0; i < 4; ++i) {
                    float v = bias;
#pragma unroll
                    for (int f = 0; f < 7; ++f) v += xr[i][f] * w[f];
                    buf[(rowgrp * 4 + i) * BUFS + c] = fmaxf(v, 0.f);
                }
            }
        }
        __syncthreads();

        const int r0 = warp * 16 + rql;
        for (int ks = 0; ks < 16; ++ks) {
            if (ks < 15) {   // produce slice ks+1
                float* buf = sBuf + ((ks + 1) & 1) * (128 * BUFS);
                const int k0 = (ks + 1) * 16;
#pragma unroll
                for (int cc = 0; cc < 2; ++cc) {
                    const int c = c2 + cc * 8;
                    float w[7];
#pragma unroll
                    for (int f = 0; f < 6; ++f) w[f] = W0g[f * 256 + k0 + c];
                    w[6] = (ptype == 2) ? 0.f : W0g[6 * 256 + k0 + c];
                    const float bias = b0g[k0 + c];
#pragma unroll
                    for (int i = 0; i < 4; ++i) {
                        float v = bias;
#pragma unroll
                        for (int f = 0; f < 7; ++f) v += xr[i][f] * w[f];
                        buf[(rowgrp * 4 + i) * BUFS + c] = fmaxf(v, 0.f);
                    }
                }
            }
            // consume slice ks
            {
                const float* buf = sBuf + (ks & 1) * (128 * BUFS);
                float2 p00 = *reinterpret_cast<const float2*>(&buf[r0 * BUFS + 2 * t4]);
                float2 p01 = *reinterpret_cast<const float2*>(&buf[r0 * BUFS + 2 * t4 + 8]);
                float2 p10 = *reinterpret_cast<const float2*>(&buf[(r0 + 8) * BUFS + 2 * t4]);
                float2 p11 = *reinterpret_cast<const float2*>(&buf[(r0 + 8) * BUFS + 2 * t4 + 8]);
                uint32_t ah0, al0, ah1, al1, ah2, al2, ah3, al3;
                split_pair(p00.x, p00.y, ah0, al0);
                split_pair(p10.x, p10.y, ah1, al1);
                split_pair(p01.x, p01.y, ah2, al2);
                split_pair(p11.x, p11.y, ah3, al3);

                const uint4* Bp = g_Bfrag + (((tI * 16 + ks) * 16 + nh * 8) * 32) + lane;
#pragma unroll
                for (int nt = 0; nt < 8; ++nt) {
                    uint4 v = Bp[nt * 32];
                    mma_bf16(acc[nt][0], acc[nt][1], acc[nt][2], acc[nt][3],
                             ah0, ah1, ah2, ah3, v.x, v.y);
                    mma_bf16(acc[nt][0], acc[nt][1], acc[nt][2], acc[nt][3],
                             al0, al1, al2, al3, v.x, v.y);
                    mma_bf16(acc[nt][0], acc[nt][1], acc[nt][2], acc[nt][3],
                             ah0, ah1, ah2, ah3, v.z, v.w);
                }
            }
            __syncthreads();
        }

        // bias + relu -> sE (half-N tile, local cols 0..63)
        {
#pragma unroll
            for (int nt = 0; nt < 8; ++nt) {
                const int c = nt * 8 + 2 * t4;
                const float be = b1g[nh * 64 + c], bo = b1g[nh * 64 + c + 1];
                float2 e0, e1;
                e0.x = fmaxf(acc[nt][0] + be, 0.f);
                e0.y = fmaxf(acc[nt][1] + bo, 0.f);
                e1.x = fmaxf(acc[nt][2] + be, 0.f);
                e1.y = fmaxf(acc[nt][3] + bo, 0.f);
                *reinterpret_cast<float2*>(&sE[r0 * SES + c]) = e0;
                *reinterpret_cast<float2*>(&sE[(r0 + 8) * SES + c]) = e1;
            }
        }
        __syncthreads();

        // per-batch sums -> sESS (+=), segment tables per group
        {
            const int c = tid & 63, slot = tid >> 6;
            const int nsegs = (g == 0) ? 7 : 10;
            for (int i = slot; i < nsegs; i += 4) {
                int s, e, b, off;
                if (g == 0) { s = 20 * i; e = min(128, s + 20); b = i; off = 128; }
                else if (i == 0) { s = 0; e = 12; b = 6; off = 128; }
                else if (i == 1) { s = 12; e = 32; b = 7; off = 128; }
                else { int j = i - 2; s = 32 + 10 * j; e = s + 10; b = j; off = 256; }
                float sum = 0.f;
                for (int r = s; r < e; ++r) sum += sE[r * SES + c];
                sESS[b * 384 + off + nh * 64 + c] += sum;
            }
        }
        // er copy (group 1 only)
        if (g == 1) {
            for (int i = tid; i < 512; i += NT) {
                int b = i >> 6, c = i & 63;
                sESS[b * 384 + nh * 64 + c] = sE[(112 + b) * SES + c];
            }
        }
        // e2 = e @ M (accumulate over halves)
        {
            const int cq = tid & 7, rs = tid >> 3;
            const int nrowmax = (g == 0) ? 128 : 112;
#pragma unroll
            for (int j = 0; j < 4; ++j) {
                const int r = rs + j * 32;
                if (r >= nrowmax) break;
                const int absr = g * 128 + r;
                int b, node;
                const float* Mg;
                if (absr < 160) { b = absr / 20; node = absr % 20; Mg = g_Mh; }
                else { int idx = absr - 160; b = idx / 10; node = 20 + idx % 10; Mg = g_Mo; }
                const float4* M4 = reinterpret_cast<const float4*>(Mg) + cq;
                const float* Er = &sE[r * SES];
                float4 a4 = make_float4(0.f, 0.f, 0.f, 0.f);
#pragma unroll 4
                for (int k = 0; k < 64; ++k) {
                    const float ev = Er[k];
                    const float4 w4 = M4[(nh * 64 + k) * 8];
                    a4.x += ev * w4.x; a4.y += ev * w4.y;
                    a4.z += ev * w4.z; a4.w += ev * w4.w;
                }
                float4* dst = reinterpret_cast<float4*>(&sE2[b * 960 + node * 32]) + cq;
                if (nh == 0) *dst = a4;
                else {
                    float4 p = *dst;
                    p.x += a4.x; p.y += a4.y; p.z += a4.z; p.w += a4.w;
                    *dst = p;
                }
            }
        }
        __syncthreads();
    }

    // ---- conv1 commons + per-node relu sums -> sVEC ----
    {
        const int b = tid >> 5, c0 = tid & 31;
        float a0 = g_Gb[c0], a1 = g_Gb[c0 + 32], a2 = g_Gb[c0 + 64];
        const float* in = &sESS[b * 384];
#pragma unroll 4
        for (int k = 0; k < 384; ++k) {
            const float av = in[k];
            a0 += av * g_G[k * 96 + c0];
            a1 += av * g_G[k * 96 + c0 + 32];
            a2 += av * g_G[k * 96 + c0 + 64];
        }
        float sh2 = 0.f, so2 = 0.f;
        const float* e2b = &sE2[b * 960];
#pragma unroll
        for (int n = 0; n < 20; ++n) sh2 += fmaxf(a0 + e2b[n * 32 + c0], 0.f);
#pragma unroll
        for (int n = 0; n < 10; ++n) so2 += fmaxf(a1 + e2b[(20 + n) * 32 + c0], 0.f);
        sVEC[b * 96 + c0]      = sh2;
        sVEC[b * 96 + 32 + c0] = so2;
        sVEC[b * 96 + 64 + c0] = fmaxf(a2, 0.f);
    }
    __syncthreads();

    // ---- hr = relu([sh2|so2|r1] @ G2 + b2) -> sE[0..1023] ----
    {
        const int b = tid >> 5, cg = tid & 31;
        float a[4];
#pragma unroll
        for (int j = 0; j < 4; ++j) a[j] = g_b2[cg + 32 * j];
        const float* in = &sVEC[b * 96];
#pragma unroll 4
        for (int k = 0; k < 96; ++k) {
            const float av = in[k];
#pragma unroll
            for (int j = 0; j < 4; ++j) a[j] += av * g_G2[k * 128 + cg + 32 * j];
        }
#pragma unroll
        for (int j = 0; j < 4; ++j)
            sE[b * 128 + cg + 32 * j] = fmaxf(a[j], 0.f);
    }
    __syncthreads();

    // ---- value MLP ----
    {
        const int col = tid;
        float a[8];
        const float bias = vb0[col];
#pragma unroll
        for (int i = 0; i < 8; ++i) a[i] = bias;
#pragma unroll 4
        for (int k = 0; k < 128; ++k) {
            const float w = vW0[k * 256 + col];
#pragma unroll
            for (int i = 0; i < 8; ++i) a[i] += sE[i * 128 + k] * w;
        }
#pragma unroll
        for (int i = 0; i < 8; ++i)
            sE2[i * 256 + col] = fmaxf(a[i], 0.f);
    }
    __syncthreads();
    {
        const int col = tid & 127, gq = tid >> 7;
        float a[4];
        const float bias = vb1[col];
#pragma unroll
        for (int i = 0; i < 4; ++i) a[i] = bias;
#pragma unroll 4
        for (int k = 0; k < 256; ++k) {
            const float w = vW1[k * 128 + col];
#pragma unroll
            for (int i = 0; i < 4; ++i) a[i] += sE2[(gq * 4 + i) * 256 + k] * w;
        }
#pragma unroll
        for (int i = 0; i < 4; ++i)
            sE2[2048 + (gq * 4 + i) * 128 + col] = fmaxf(a[i], 0.f);
    }
    __syncthreads();
    {
        const int b = warp, l = lane;
        float s = 0.f;
#pragma unroll
        for (int k = l; k < 128; k += 32) s += sE2[2048 + b * 128 + k] * vW2[k];
#pragma unroll
        for (int off = 16; off > 0; off >>= 1)
            s += __shfl_down_sync(0xffffffffu, s, off);
        if (l == 0) out[b0 + b] = s + vb2[0];
    }
}

// ============================================================
extern "C" void kernel_launch(void* const* d_in, const int* in_sizes, int n_in,
                              void* d_out, int out_size) {
    const float* state   = (const float*)d_in[0];
    const float* wrW0    = (const float*)d_in[2];
    const float* wrb0    = (const float*)d_in[3];
    const float* wrW1    = (const float*)d_in[4];
    const float* wrb1    = (const float*)d_in[5];
    const float* whW0    = (const float*)d_in[6];
    const float* whb0    = (const float*)d_in[7];
    const float* whW1    = (const float*)d_in[8];
    const float* whb1    = (const float*)d_in[9];
    const float* woW0    = (const float*)d_in[10];
    const float* wob0    = (const float*)d_in[11];
    const float* woW1    = (const float*)d_in[12];
    const float* wob1    = (const float*)d_in[13];
    const float* c1_relW = (const float*)d_in[14];
    const float* c1_relb = (const float*)d_in[15];
    const float* c1_rootW= (const float*)d_in[16];
    const float* c2_relW = (const float*)d_in[17];
    const float* c2_relb = (const float*)d_in[18];
    const float* c2_rootW= (const float*)d_in[19];
    const float* vW0     = (const float*)d_in[20];
    const float* vb0     = (const float*)d_in[21];
    const float* vW1     = (const float*)d_in[22];
    const float* vb1     = (const float*)d_in[23];
    const float* vW2     = (const float*)d_in[24];
    const float* vb2     = (const float*)d_in[25];
    float* out = (float*)d_out;

    cudaFuncSetAttribute(main_kernel, cudaFuncAttributeMaxDynamicSharedMemorySize,
                         MAIN_SMEM_FLOATS * 4);

    prep_kernel<<<96, 256>>>(c1_relW, c1_relb, c1_rootW, c2_relW, c2_relb, c2_rootW,
                             whW1, woW1, wrW1);

    main_kernel<<<BATCH / BT, NT, MAIN_SMEM_FLOATS * 4>>>(
        state, wrW0, wrb0, wrb1, whW0, whb0, whb1,
        woW0, wob0, wob1,
        vW0, vb0, vW1, vb1, vW2, vb2, out);
}